// round 2
// baseline (speedup 1.0000x reference)
#include <cuda_runtime.h>
#include <cstdint>

// MLRAttention: x@W_attn+b -> split q,k,v -> multi-level block-diag low-rank
// scores -> causal softmax -> @v -> @W_proj+b.
//
// T=2048, D_MODEL=1024, 16 heads x 64 dims.
// Levels: dims [0,32) scale 1/32 block 2048; [32,48) 1/16 block 1024;
//         [48,56) 1/8 block 512; [56,64) 1/8 block 256.
// For a (q-tile, k-tile) pair of 64 rows/cols, effective depth D is constant:
//   same 256-block -> 64, same 512 -> 56, same 1024 -> 48, else 32.

#define T_SEQ 2048
#define DMODEL 1024
#define NHEAD 16

// Scratch (no cudaMalloc allowed)
__device__ float g_qkv[T_SEQ * 3 * DMODEL];   // 25 MB
__device__ float g_y[T_SEQ * DMODEL];         // 8 MB

// ---------------------------------------------------------------------------
// Tiled fp32 SGEMM with bias: C[M,N] = A[M,K] @ B[K,N] + bias[N]
// BM=BN=128, BK=16, 256 threads, 8x8 microtile.
// ---------------------------------------------------------------------------
__global__ __launch_bounds__(256, 2)
void sgemm_bias_kernel(const float* __restrict__ A, const float* __restrict__ B,
                       const float* __restrict__ bias, float* __restrict__ C,
                       int M, int N, int K)
{
    constexpr int BM = 128, BN = 128, BK = 16;
    __shared__ float As[BK][BM];   // A stored transposed
    __shared__ float Bs[BK][BN];

    const int tid = threadIdx.x;
    const int tx = tid & 15, ty = tid >> 4;
    const int row0 = ty * 8, col0 = tx * 8;
    const int bm = blockIdx.y, bn = blockIdx.x;

    float acc[8][8];
    #pragma unroll
    for (int i = 0; i < 8; i++)
        #pragma unroll
        for (int j = 0; j < 8; j++) acc[i][j] = 0.f;

    const float* Ab = A + (size_t)bm * BM * K;
    const float* Bb = B + (size_t)bn * BN;

    for (int k0 = 0; k0 < K; k0 += BK) {
        // A tile: 128x16 floats = 512 float4, 2 per thread
        #pragma unroll
        for (int i = 0; i < 2; i++) {
            int f = tid + i * 256;
            int r = f >> 2, c4 = (f & 3) << 2;
            float4 v = *(const float4*)(Ab + (size_t)r * K + k0 + c4);
            As[c4 + 0][r] = v.x;
            As[c4 + 1][r] = v.y;
            As[c4 + 2][r] = v.z;
            As[c4 + 3][r] = v.w;
        }
        // B tile: 16x128 floats = 512 float4, 2 per thread
        #pragma unroll
        for (int i = 0; i < 2; i++) {
            int f = tid + i * 256;
            int r = f >> 5, c4 = (f & 31) << 2;
            *(float4*)(&Bs[r][c4]) = *(const float4*)(Bb + (size_t)(k0 + r) * N + c4);
        }
        __syncthreads();

        #pragma unroll
        for (int k = 0; k < BK; k++) {
            float a[8], b[8];
            *(float4*)(a)     = *(float4*)(&As[k][row0]);
            *(float4*)(a + 4) = *(float4*)(&As[k][row0 + 4]);
            *(float4*)(b)     = *(float4*)(&Bs[k][col0]);
            *(float4*)(b + 4) = *(float4*)(&Bs[k][col0 + 4]);
            #pragma unroll
            for (int i = 0; i < 8; i++)
                #pragma unroll
                for (int j = 0; j < 8; j++)
                    acc[i][j] = fmaf(a[i], b[j], acc[i][j]);
        }
        __syncthreads();
    }

    #pragma unroll
    for (int i = 0; i < 8; i++) {
        size_t r = (size_t)(bm * BM + row0 + i);
        #pragma unroll
        for (int j = 0; j < 8; j += 4) {
            int c = bn * BN + col0 + j;
            float4 v;
            v.x = acc[i][j + 0] + bias[c + 0];
            v.y = acc[i][j + 1] + bias[c + 1];
            v.z = acc[i][j + 2] + bias[c + 2];
            v.w = acc[i][j + 3] + bias[c + 3];
            *(float4*)(C + r * N + c) = v;
        }
    }
}

// ---------------------------------------------------------------------------
// Flash attention over 64x64 tiles with per-tile-pair effective depth D.
// Grid: (32 q-tiles, 16 heads), 256 threads, each thread a 4x4 microtile
// (16x16 thread grid; row-reductions via shfl over the 16 tx lanes).
// Smem: Qs[64][64], KPs[64][64] (K^T scaled, reused as P), Vs[64][64] = 48KB.
// ---------------------------------------------------------------------------
__global__ __launch_bounds__(256)
void mlr_attn_kernel(const float* __restrict__ qkv, float* __restrict__ y)
{
    __shared__ float Qs[64 * 64];
    __shared__ float KPs[64 * 64];   // K transposed [d][c]; later P [r][s]
    __shared__ float Vs[64 * 64];    // [s][d]

    const int tid = threadIdx.x;
    const int tx = tid & 15, ty = tid >> 4;
    const int r0 = ty * 4;           // local row base
    const int c0 = tx * 4;           // local col base
    const int h = blockIdx.y;
    const int qt = gridDim.x - 1 - blockIdx.x;   // heavy (long-row) blocks first

    // Load Q tile: rows = tokens, cols = head dims
    #pragma unroll
    for (int i = 0; i < 4; i++) {
        int f = tid + i * 256;                 // 1024 float4 total
        int r = f >> 4, c4 = (f & 15) << 2;
        *(float4*)&Qs[r * 64 + c4] =
            *(const float4*)(qkv + (size_t)(qt * 64 + r) * 3072 + h * 64 + c4);
    }

    float m[4], l[4], O[4][4];
    #pragma unroll
    for (int i = 0; i < 4; i++) {
        m[i] = -1e30f; l[i] = 0.f;
        #pragma unroll
        for (int j = 0; j < 4; j++) O[i][j] = 0.f;
    }

    for (int kt = 0; kt <= qt; kt++) {
        __syncthreads();   // previous iteration readers of KPs/Vs are done

        // Load K (transposed + per-level scale) and V
        #pragma unroll
        for (int i = 0; i < 4; i++) {
            int f = tid + i * 256;
            int c = f >> 4, d4 = (f & 15) << 2;   // d4 in {0,4,...,60}
            const float* base = qkv + (size_t)(kt * 64 + c) * 3072 + h * 64 + d4;
            float4 kv = *(const float4*)(base + 1024);
            // region boundaries 32/48/56 are multiples of 4 -> one scale per float4
            float sc = (d4 < 32) ? 0.03125f : (d4 < 48) ? 0.0625f : 0.125f;
            KPs[(d4 + 0) * 64 + c] = kv.x * sc;
            KPs[(d4 + 1) * 64 + c] = kv.y * sc;
            KPs[(d4 + 2) * 64 + c] = kv.z * sc;
            KPs[(d4 + 3) * 64 + c] = kv.w * sc;
            *(float4*)&Vs[c * 64 + d4] = *(const float4*)(base + 2048);
        }
        __syncthreads();

        const int D = ((qt >> 2) == (kt >> 2)) ? 64
                    : ((qt >> 3) == (kt >> 3)) ? 56
                    : ((qt >> 4) == (kt >> 4)) ? 48 : 32;

        float s[4][4];
        #pragma unroll
        for (int i = 0; i < 4; i++)
            #pragma unroll
            for (int j = 0; j < 4; j++) s[i][j] = 0.f;

        #pragma unroll 8
        for (int d = 0; d < D; d++) {
            float4 kv = *(float4*)&KPs[d * 64 + c0];
            float q[4];
            #pragma unroll
            for (int i = 0; i < 4; i++) q[i] = Qs[(r0 + i) * 64 + d];
            #pragma unroll
            for (int i = 0; i < 4; i++) {
                s[i][0] = fmaf(q[i], kv.x, s[i][0]);
                s[i][1] = fmaf(q[i], kv.y, s[i][1]);
                s[i][2] = fmaf(q[i], kv.z, s[i][2]);
                s[i][3] = fmaf(q[i], kv.w, s[i][3]);
            }
        }

        if (kt == qt) {   // causal mask on diagonal tile
            #pragma unroll
            for (int i = 0; i < 4; i++)
                #pragma unroll
                for (int j = 0; j < 4; j++)
                    if (c0 + j > r0 + i) s[i][j] = -1e30f;
        }

        // Online softmax (row reductions over the 16 tx lanes of this warp half)
        float p[4][4];
        #pragma unroll
        for (int i = 0; i < 4; i++) {
            float mx = fmaxf(fmaxf(s[i][0], s[i][1]), fmaxf(s[i][2], s[i][3]));
            #pragma unroll
            for (int off = 8; off >= 1; off >>= 1)
                mx = fmaxf(mx, __shfl_xor_sync(0xffffffffu, mx, off));
            float mn = fmaxf(m[i], mx);
            float corr = __expf(m[i] - mn);
            m[i] = mn;
            float ls = 0.f;
            #pragma unroll
            for (int j = 0; j < 4; j++) { p[i][j] = __expf(s[i][j] - mn); ls += p[i][j]; }
            #pragma unroll
            for (int off = 8; off >= 1; off >>= 1)
                ls += __shfl_xor_sync(0xffffffffu, ls, off);
            l[i] = l[i] * corr + ls;
            #pragma unroll
            for (int j = 0; j < 4; j++) O[i][j] *= corr;
        }

        __syncthreads();   // everyone done reading KPs (K^T) -> reuse as P
        #pragma unroll
        for (int i = 0; i < 4; i++)
            *(float4*)&KPs[(r0 + i) * 64 + c0] = *(float4*)&p[i][0];
        __syncthreads();

        // O += P @ V   (O dims: cols c0..c0+3 of head)
        #pragma unroll 8
        for (int ss = 0; ss < 64; ss++) {
            float4 vv = *(float4*)&Vs[ss * 64 + c0];
            float pv[4];
            #pragma unroll
            for (int i = 0; i < 4; i++) pv[i] = KPs[(r0 + i) * 64 + ss];
            #pragma unroll
            for (int i = 0; i < 4; i++) {
                O[i][0] = fmaf(pv[i], vv.x, O[i][0]);
                O[i][1] = fmaf(pv[i], vv.y, O[i][1]);
                O[i][2] = fmaf(pv[i], vv.z, O[i][2]);
                O[i][3] = fmaf(pv[i], vv.w, O[i][3]);
            }
        }
    }

    // Epilogue: normalize and write y[t][h*64 + d]
    #pragma unroll
    for (int i = 0; i < 4; i++) {
        float inv = 1.f / l[i];
        float4 v;
        v.x = O[i][0] * inv;
        v.y = O[i][1] * inv;
        v.z = O[i][2] * inv;
        v.w = O[i][3] * inv;
        *(float4*)(y + (size_t)(qt * 64 + r0 + i) * DMODEL + h * 64 + c0) = v;
    }
}

// ---------------------------------------------------------------------------
extern "C" void kernel_launch(void* const* d_in, const int* in_sizes, int n_in,
                              void* d_out, int out_size)
{
    const float* x      = (const float*)d_in[0];   // (1,2048,1024)
    const float* W_attn = (const float*)d_in[1];   // (1024,3072)
    const float* b_attn = (const float*)d_in[2];   // (3072)
    const float* W_proj = (const float*)d_in[3];   // (1024,1024)
    const float* b_proj = (const float*)d_in[4];   // (1024)
    float* out = (float*)d_out;                    // (1,2048,1024)

    float* qkv; cudaGetSymbolAddress((void**)&qkv, g_qkv);
    float* yb;  cudaGetSymbolAddress((void**)&yb,  g_y);

    // 1) qkv = x @ W_attn + b_attn     [2048 x 3072]
    sgemm_bias_kernel<<<dim3(3072 / 128, 2048 / 128), 256>>>(
        x, W_attn, b_attn, qkv, T_SEQ, 3 * DMODEL, DMODEL);

    // 2) y = MLR-attention(qkv)        [2048 x 1024]
    mlr_attn_kernel<<<dim3(T_SEQ / 64, NHEAD), 256>>>(qkv, yb);

    // 3) out = y @ W_proj + b_proj     [2048 x 1024]
    sgemm_bias_kernel<<<dim3(1024 / 128, 2048 / 128), 256>>>(
        yb, W_proj, b_proj, out, T_SEQ, DMODEL, DMODEL);
}

// round 4
// speedup vs baseline: 1.3229x; 1.3229x over previous
#include <cuda_runtime.h>
#include <cuda_bf16.h>
#include <cstdint>

// MLRAttention, round 4: GEMMs on tensor cores via portable mma.sync (sm_80 PTX,
// works on sm_100 baseline target -- tcgen05 needs the '100a' feature target the
// harness doesn't use). Split-bf16 (3 passes: Ah*Bh + Ah*Bl + Al*Bh) gives
// ~1.5e-5 relative accuracy with fp32 accumulation.

#define T_SEQ 2048
#define DMODEL 1024
#define NHEAD 16

__device__ float g_qkv[T_SEQ * 3 * DMODEL];
__device__ float g_y[T_SEQ * DMODEL];

__device__ __forceinline__ uint32_t smem_u32(const void* p) {
    uint32_t a;
    asm("{ .reg .u64 t; cvta.to.shared.u64 t, %1; cvt.u32.u64 %0, t; }"
        : "=r"(a) : "l"(p));
    return a;
}

#define LDMATRIX_X4(r0, r1, r2, r3, addr) \
    asm volatile("ldmatrix.sync.aligned.m8n8.x4.shared.b16 {%0,%1,%2,%3}, [%4];" \
                 : "=r"(r0), "=r"(r1), "=r"(r2), "=r"(r3) : "r"(addr))

#define LDMATRIX_X4_T(r0, r1, r2, r3, addr) \
    asm volatile("ldmatrix.sync.aligned.m8n8.x4.trans.shared.b16 {%0,%1,%2,%3}, [%4];" \
                 : "=r"(r0), "=r"(r1), "=r"(r2), "=r"(r3) : "r"(addr))

#define MMA_BF16(d, a, b) \
    asm volatile("mma.sync.aligned.m16n8k16.row.col.f32.bf16.bf16.f32 " \
                 "{%0,%1,%2,%3}, {%4,%5,%6,%7}, {%8,%9}, {%0,%1,%2,%3};" \
                 : "+f"((d)[0]), "+f"((d)[1]), "+f"((d)[2]), "+f"((d)[3]) \
                 : "r"((a)[0]), "r"((a)[1]), "r"((a)[2]), "r"((a)[3]), \
                   "r"((b)[0]), "r"((b)[1]))

__device__ __forceinline__ float bf_lo(float v) {
    return v - __bfloat162float(__float2bfloat16(v));
}
__device__ __forceinline__ uint32_t pack2(float a, float b) {
    return ((uint32_t)__bfloat16_as_ushort(__float2bfloat16(b)) << 16) |
           (uint32_t)__bfloat16_as_ushort(__float2bfloat16(a));
}

// ---------------------------------------------------------------------------
// Split-bf16 tensor-core GEMM: C[M,N] = A[M,K] @ W[K,N] + bias.
// BM=BN=128, BK=32, 256 threads (8 warps, warp tile 64x32), double-buffered.
// Smem (uint16 units): per buffer: Ah[128*40] Al[128*40] Bh[32*136] Bl[32*136].
// Padded strides (80B / 272B) keep ldmatrix conflict-free.
// ---------------------------------------------------------------------------
#define SA 40
#define SB 136
#define A_SZ (128 * SA)                 // 5120 u16
#define B_SZ (32 * SB)                  // 4352 u16
#define BUF_SZ (2 * A_SZ + 2 * B_SZ)    // 18944 u16 = 37888 B
#define GEMM_SMEM_BYTES (2 * BUF_SZ * 2)

__global__ __launch_bounds__(256)
void tc_gemm_bias_kernel(const float* __restrict__ A, const float* __restrict__ W,
                         const float* __restrict__ bias, float* __restrict__ C,
                         int K, int N)
{
    extern __shared__ uint16_t sm[];
    const uint32_t sbase = smem_u32(sm);
    const int tid = threadIdx.x;
    const int lane = tid & 31;
    const int wid = tid >> 5;
    const int wm = wid & 1, wn = wid >> 1;     // warp tile: (wm*64, wn*32)
    const int bm = blockIdx.y, bn = blockIdx.x;

    float acc[4][4][4];
    #pragma unroll
    for (int i = 0; i < 4; i++)
        #pragma unroll
        for (int j = 0; j < 4; j++)
            #pragma unroll
            for (int t = 0; t < 4; t++) acc[i][j][t] = 0.f;

    const int KT = K >> 5;

    // gmem load coords (4 float4 each for A and B per thread)
    const int a_row = tid >> 3, a_kq = (tid & 7) * 4;       // + i*32 rows
    const int b_krow = tid >> 5, b_nq = (tid & 31) * 4;     // + i*8 rows
    const float* Ag = A + (size_t)(bm * 128) * K;
    const float* Bg = W + (size_t)(bn * 128);

    float4 astg[4], bstg[4];

    // ---- prologue: load tile 0 ----
    #pragma unroll
    for (int i = 0; i < 4; i++) {
        astg[i] = *(const float4*)(Ag + (size_t)(a_row + i * 32) * K + a_kq);
        bstg[i] = *(const float4*)(Bg + (size_t)(b_krow + i * 8) * N + b_nq);
    }
    #pragma unroll
    for (int i = 0; i < 4; i++) {
        uint16_t* Ah = sm;                 uint16_t* Al = sm + A_SZ;
        uint16_t* Bh = sm + 2 * A_SZ;      uint16_t* Bl = sm + 2 * A_SZ + B_SZ;
        float4 v = astg[i];
        int ao = (a_row + i * 32) * SA + a_kq;
        *(uint2*)(Ah + ao) = make_uint2(pack2(v.x, v.y), pack2(v.z, v.w));
        *(uint2*)(Al + ao) = make_uint2(pack2(bf_lo(v.x), bf_lo(v.y)),
                                        pack2(bf_lo(v.z), bf_lo(v.w)));
        float4 w = bstg[i];
        int bo = (b_krow + i * 8) * SB + b_nq;
        *(uint2*)(Bh + bo) = make_uint2(pack2(w.x, w.y), pack2(w.z, w.w));
        *(uint2*)(Bl + bo) = make_uint2(pack2(bf_lo(w.x), bf_lo(w.y)),
                                        pack2(bf_lo(w.z), bf_lo(w.w)));
    }
    __syncthreads();

    for (int kt = 0; kt < KT; kt++) {
        const int b = kt & 1;
        const uint32_t bufb = sbase + b * BUF_SZ * 2;       // byte base
        const uint32_t pAh = bufb, pAl = bufb + A_SZ * 2;
        const uint32_t pBh = bufb + 4 * A_SZ, pBl = pBh + B_SZ * 2;

        // issue next tile's gmem loads early
        if (kt + 1 < KT) {
            const int k0 = (kt + 1) << 5;
            #pragma unroll
            for (int i = 0; i < 4; i++) {
                astg[i] = *(const float4*)(Ag + (size_t)(a_row + i * 32) * K + k0 + a_kq);
                bstg[i] = *(const float4*)(Bg + (size_t)(b_krow + k0 + i * 8) * N + b_nq);
            }
        }

        // ---- compute on buffer b ----
        #pragma unroll
        for (int ks = 0; ks < 32; ks += 16) {
            uint32_t ah[4][4], al[4][4], bh[4][2], bl[4][2];
            #pragma unroll
            for (int i = 0; i < 4; i++) {
                uint32_t off = ((wm * 64 + i * 16 + (lane & 15)) * SA
                                + ks + (lane >> 4) * 8) * 2;
                LDMATRIX_X4(ah[i][0], ah[i][1], ah[i][2], ah[i][3], pAh + off);
                LDMATRIX_X4(al[i][0], al[i][1], al[i][2], al[i][3], pAl + off);
            }
            #pragma unroll
            for (int j2 = 0; j2 < 2; j2++) {   // each covers two n8 tiles
                uint32_t off = ((ks + (lane & 15)) * SB
                                + wn * 32 + j2 * 16 + (lane >> 4) * 8) * 2;
                LDMATRIX_X4_T(bh[j2 * 2][0], bh[j2 * 2][1],
                              bh[j2 * 2 + 1][0], bh[j2 * 2 + 1][1], pBh + off);
                LDMATRIX_X4_T(bl[j2 * 2][0], bl[j2 * 2][1],
                              bl[j2 * 2 + 1][0], bl[j2 * 2 + 1][1], pBl + off);
            }
            #pragma unroll
            for (int i = 0; i < 4; i++)
                #pragma unroll
                for (int j = 0; j < 4; j++) {
                    MMA_BF16(acc[i][j], ah[i], bh[j]);
                    MMA_BF16(acc[i][j], ah[i], bl[j]);
                    MMA_BF16(acc[i][j], al[i], bh[j]);
                }
        }
        __syncthreads();

        // ---- store next tile into buffer b^1 ----
        if (kt + 1 < KT) {
            uint16_t* base = sm + (b ^ 1) * BUF_SZ;
            uint16_t* Ah = base;             uint16_t* Al = base + A_SZ;
            uint16_t* Bh = base + 2 * A_SZ;  uint16_t* Bl = base + 2 * A_SZ + B_SZ;
            #pragma unroll
            for (int i = 0; i < 4; i++) {
                float4 v = astg[i];
                int ao = (a_row + i * 32) * SA + a_kq;
                *(uint2*)(Ah + ao) = make_uint2(pack2(v.x, v.y), pack2(v.z, v.w));
                *(uint2*)(Al + ao) = make_uint2(pack2(bf_lo(v.x), bf_lo(v.y)),
                                                pack2(bf_lo(v.z), bf_lo(v.w)));
                float4 w = bstg[i];
                int bo = (b_krow + i * 8) * SB + b_nq;
                *(uint2*)(Bh + bo) = make_uint2(pack2(w.x, w.y), pack2(w.z, w.w));
                *(uint2*)(Bl + bo) = make_uint2(pack2(bf_lo(w.x), bf_lo(w.y)),
                                                pack2(bf_lo(w.z), bf_lo(w.w)));
            }
            __syncthreads();
        }
    }

    // ---- epilogue ----
    const int g = lane >> 2, c = (lane & 3) * 2;
    #pragma unroll
    for (int i = 0; i < 4; i++) {
        #pragma unroll
        for (int j = 0; j < 4; j++) {
            int row = bm * 128 + wm * 64 + i * 16 + g;
            int col = bn * 128 + wn * 32 + j * 8 + c;
            float b0 = bias[col], b1 = bias[col + 1];
            *(float2*)(C + (size_t)row * N + col) =
                make_float2(acc[i][j][0] + b0, acc[i][j][1] + b1);
            *(float2*)(C + (size_t)(row + 8) * N + col) =
                make_float2(acc[i][j][2] + b0, acc[i][j][3] + b1);
        }
    }
}

// ---------------------------------------------------------------------------
// Flash attention over 64x64 tiles (unchanged from round 2).
// ---------------------------------------------------------------------------
__global__ __launch_bounds__(256)
void mlr_attn_kernel(const float* __restrict__ qkv, float* __restrict__ y)
{
    __shared__ float Qs[64 * 64];
    __shared__ float KPs[64 * 64];
    __shared__ float Vs[64 * 64];

    const int tid = threadIdx.x;
    const int tx = tid & 15, ty = tid >> 4;
    const int r0 = ty * 4;
    const int c0 = tx * 4;
    const int h = blockIdx.y;
    const int qt = gridDim.x - 1 - blockIdx.x;

    #pragma unroll
    for (int i = 0; i < 4; i++) {
        int f = tid + i * 256;
        int r = f >> 4, c4 = (f & 15) << 2;
        *(float4*)&Qs[r * 64 + c4] =
            *(const float4*)(qkv + (size_t)(qt * 64 + r) * 3072 + h * 64 + c4);
    }

    float m[4], l[4], O[4][4];
    #pragma unroll
    for (int i = 0; i < 4; i++) {
        m[i] = -1e30f; l[i] = 0.f;
        #pragma unroll
        for (int j = 0; j < 4; j++) O[i][j] = 0.f;
    }

    for (int kt = 0; kt <= qt; kt++) {
        __syncthreads();

        #pragma unroll
        for (int i = 0; i < 4; i++) {
            int f = tid + i * 256;
            int cc = f >> 4, d4 = (f & 15) << 2;
            const float* base = qkv + (size_t)(kt * 64 + cc) * 3072 + h * 64 + d4;
            float4 kv = *(const float4*)(base + 1024);
            float sc = (d4 < 32) ? 0.03125f : (d4 < 48) ? 0.0625f : 0.125f;
            KPs[(d4 + 0) * 64 + cc] = kv.x * sc;
            KPs[(d4 + 1) * 64 + cc] = kv.y * sc;
            KPs[(d4 + 2) * 64 + cc] = kv.z * sc;
            KPs[(d4 + 3) * 64 + cc] = kv.w * sc;
            *(float4*)&Vs[cc * 64 + d4] = *(const float4*)(base + 2048);
        }
        __syncthreads();

        const int D = ((qt >> 2) == (kt >> 2)) ? 64
                    : ((qt >> 3) == (kt >> 3)) ? 56
                    : ((qt >> 4) == (kt >> 4)) ? 48 : 32;

        float s[4][4];
        #pragma unroll
        for (int i = 0; i < 4; i++)
            #pragma unroll
            for (int j = 0; j < 4; j++) s[i][j] = 0.f;

        #pragma unroll 8
        for (int d = 0; d < D; d++) {
            float4 kv = *(float4*)&KPs[d * 64 + c0];
            float q[4];
            #pragma unroll
            for (int i = 0; i < 4; i++) q[i] = Qs[(r0 + i) * 64 + d];
            #pragma unroll
            for (int i = 0; i < 4; i++) {
                s[i][0] = fmaf(q[i], kv.x, s[i][0]);
                s[i][1] = fmaf(q[i], kv.y, s[i][1]);
                s[i][2] = fmaf(q[i], kv.z, s[i][2]);
                s[i][3] = fmaf(q[i], kv.w, s[i][3]);
            }
        }

        if (kt == qt) {
            #pragma unroll
            for (int i = 0; i < 4; i++)
                #pragma unroll
                for (int j = 0; j < 4; j++)
                    if (c0 + j > r0 + i) s[i][j] = -1e30f;
        }

        float p[4][4];
        #pragma unroll
        for (int i = 0; i < 4; i++) {
            float mx = fmaxf(fmaxf(s[i][0], s[i][1]), fmaxf(s[i][2], s[i][3]));
            #pragma unroll
            for (int off = 8; off >= 1; off >>= 1)
                mx = fmaxf(mx, __shfl_xor_sync(0xffffffffu, mx, off));
            float mn = fmaxf(m[i], mx);
            float corr = __expf(m[i] - mn);
            m[i] = mn;
            float ls = 0.f;
            #pragma unroll
            for (int j = 0; j < 4; j++) { p[i][j] = __expf(s[i][j] - mn); ls += p[i][j]; }
            #pragma unroll
            for (int off = 8; off >= 1; off >>= 1)
                ls += __shfl_xor_sync(0xffffffffu, ls, off);
            l[i] = l[i] * corr + ls;
            #pragma unroll
            for (int j = 0; j < 4; j++) O[i][j] *= corr;
        }

        __syncthreads();
        #pragma unroll
        for (int i = 0; i < 4; i++)
            *(float4*)&KPs[(r0 + i) * 64 + c0] = *(float4*)&p[i][0];
        __syncthreads();

        #pragma unroll 8
        for (int ss = 0; ss < 64; ss++) {
            float4 vv = *(float4*)&Vs[ss * 64 + c0];
            float pv[4];
            #pragma unroll
            for (int i = 0; i < 4; i++) pv[i] = KPs[(r0 + i) * 64 + ss];
            #pragma unroll
            for (int i = 0; i < 4; i++) {
                O[i][0] = fmaf(pv[i], vv.x, O[i][0]);
                O[i][1] = fmaf(pv[i], vv.y, O[i][1]);
                O[i][2] = fmaf(pv[i], vv.z, O[i][2]);
                O[i][3] = fmaf(pv[i], vv.w, O[i][3]);
            }
        }
    }

    #pragma unroll
    for (int i = 0; i < 4; i++) {
        float inv = 1.f / l[i];
        float4 v;
        v.x = O[i][0] * inv;
        v.y = O[i][1] * inv;
        v.z = O[i][2] * inv;
        v.w = O[i][3] * inv;
        *(float4*)(y + (size_t)(qt * 64 + r0 + i) * DMODEL + h * 64 + c0) = v;
    }
}

// ---------------------------------------------------------------------------
extern "C" void kernel_launch(void* const* d_in, const int* in_sizes, int n_in,
                              void* d_out, int out_size)
{
    const float* x      = (const float*)d_in[0];
    const float* W_attn = (const float*)d_in[1];
    const float* b_attn = (const float*)d_in[2];
    const float* W_proj = (const float*)d_in[3];
    const float* b_proj = (const float*)d_in[4];
    float* out = (float*)d_out;

    float* qkv; cudaGetSymbolAddress((void**)&qkv, g_qkv);
    float* yb;  cudaGetSymbolAddress((void**)&yb,  g_y);

    cudaFuncSetAttribute(tc_gemm_bias_kernel,
                         cudaFuncAttributeMaxDynamicSharedMemorySize, GEMM_SMEM_BYTES);

    // 1) qkv = x @ W_attn + b_attn   [2048 x 3072]
    tc_gemm_bias_kernel<<<dim3(3072 / 128, 2048 / 128), 256, GEMM_SMEM_BYTES>>>(
        x, W_attn, b_attn, qkv, DMODEL, 3 * DMODEL);

    // 2) y = MLR-attention(qkv)      [2048 x 1024]
    mlr_attn_kernel<<<dim3(T_SEQ / 64, NHEAD), 256>>>(qkv, yb);

    // 3) out = y @ W_proj + b_proj   [2048 x 1024]
    tc_gemm_bias_kernel<<<dim3(1024 / 128, 2048 / 128), 256, GEMM_SMEM_BYTES>>>(
        yb, W_proj, b_proj, out, DMODEL, DMODEL);
}

// round 5
// speedup vs baseline: 2.1419x; 1.6191x over previous
#include <cuda_runtime.h>
#include <cuda_bf16.h>
#include <cstdint>

// MLRAttention round 5: attention moved to mma.sync bf16 (split hi/lo, 3 passes)
// like the GEMMs. Scores: Qh*Kh + Qh*Kl + Ql*Kh with per-level 1/r scale folded
// into K (powers of two -> exact). P*V: P split in registers (acc layout == A
// fragment layout), V hi/lo in smem, 3 passes.

#define T_SEQ 2048
#define DMODEL 1024
#define NHEAD 16

__device__ float g_qkv[T_SEQ * 3 * DMODEL];
__device__ float g_y[T_SEQ * DMODEL];

__device__ __forceinline__ uint32_t smem_u32(const void* p) {
    uint32_t a;
    asm("{ .reg .u64 t; cvta.to.shared.u64 t, %1; cvt.u32.u64 %0, t; }"
        : "=r"(a) : "l"(p));
    return a;
}

#define LDMATRIX_X4(r0, r1, r2, r3, addr) \
    asm volatile("ldmatrix.sync.aligned.m8n8.x4.shared.b16 {%0,%1,%2,%3}, [%4];" \
                 : "=r"(r0), "=r"(r1), "=r"(r2), "=r"(r3) : "r"(addr))

#define LDMATRIX_X4_T(r0, r1, r2, r3, addr) \
    asm volatile("ldmatrix.sync.aligned.m8n8.x4.trans.shared.b16 {%0,%1,%2,%3}, [%4];" \
                 : "=r"(r0), "=r"(r1), "=r"(r2), "=r"(r3) : "r"(addr))

#define MMA_BF16(d, a, b) \
    asm volatile("mma.sync.aligned.m16n8k16.row.col.f32.bf16.bf16.f32 " \
                 "{%0,%1,%2,%3}, {%4,%5,%6,%7}, {%8,%9}, {%0,%1,%2,%3};" \
                 : "+f"((d)[0]), "+f"((d)[1]), "+f"((d)[2]), "+f"((d)[3]) \
                 : "r"((a)[0]), "r"((a)[1]), "r"((a)[2]), "r"((a)[3]), \
                   "r"((b)[0]), "r"((b)[1]))

__device__ __forceinline__ float bf_lo(float v) {
    return v - __bfloat162float(__float2bfloat16(v));
}
__device__ __forceinline__ uint32_t pack2(float a, float b) {
    return ((uint32_t)__bfloat16_as_ushort(__float2bfloat16(b)) << 16) |
           (uint32_t)__bfloat16_as_ushort(__float2bfloat16(a));
}

// ---------------------------------------------------------------------------
// Split-bf16 tensor-core GEMM (unchanged from round 4).
// ---------------------------------------------------------------------------
#define SA 40
#define SB 136
#define A_SZ (128 * SA)
#define B_SZ (32 * SB)
#define BUF_SZ (2 * A_SZ + 2 * B_SZ)
#define GEMM_SMEM_BYTES (2 * BUF_SZ * 2)

__global__ __launch_bounds__(256)
void tc_gemm_bias_kernel(const float* __restrict__ A, const float* __restrict__ W,
                         const float* __restrict__ bias, float* __restrict__ C,
                         int K, int N)
{
    extern __shared__ uint16_t sm[];
    const uint32_t sbase = smem_u32(sm);
    const int tid = threadIdx.x;
    const int lane = tid & 31;
    const int wid = tid >> 5;
    const int wm = wid & 1, wn = wid >> 1;
    const int bm = blockIdx.y, bn = blockIdx.x;

    float acc[4][4][4];
    #pragma unroll
    for (int i = 0; i < 4; i++)
        #pragma unroll
        for (int j = 0; j < 4; j++)
            #pragma unroll
            for (int t = 0; t < 4; t++) acc[i][j][t] = 0.f;

    const int KT = K >> 5;
    const int a_row = tid >> 3, a_kq = (tid & 7) * 4;
    const int b_krow = tid >> 5, b_nq = (tid & 31) * 4;
    const float* Ag = A + (size_t)(bm * 128) * K;
    const float* Bg = W + (size_t)(bn * 128);

    float4 astg[4], bstg[4];
    #pragma unroll
    for (int i = 0; i < 4; i++) {
        astg[i] = *(const float4*)(Ag + (size_t)(a_row + i * 32) * K + a_kq);
        bstg[i] = *(const float4*)(Bg + (size_t)(b_krow + i * 8) * N + b_nq);
    }
    #pragma unroll
    for (int i = 0; i < 4; i++) {
        uint16_t* Ah = sm;                 uint16_t* Al = sm + A_SZ;
        uint16_t* Bh = sm + 2 * A_SZ;      uint16_t* Bl = sm + 2 * A_SZ + B_SZ;
        float4 v = astg[i];
        int ao = (a_row + i * 32) * SA + a_kq;
        *(uint2*)(Ah + ao) = make_uint2(pack2(v.x, v.y), pack2(v.z, v.w));
        *(uint2*)(Al + ao) = make_uint2(pack2(bf_lo(v.x), bf_lo(v.y)),
                                        pack2(bf_lo(v.z), bf_lo(v.w)));
        float4 w = bstg[i];
        int bo = (b_krow + i * 8) * SB + b_nq;
        *(uint2*)(Bh + bo) = make_uint2(pack2(w.x, w.y), pack2(w.z, w.w));
        *(uint2*)(Bl + bo) = make_uint2(pack2(bf_lo(w.x), bf_lo(w.y)),
                                        pack2(bf_lo(w.z), bf_lo(w.w)));
    }
    __syncthreads();

    for (int kt = 0; kt < KT; kt++) {
        const int b = kt & 1;
        const uint32_t bufb = sbase + b * BUF_SZ * 2;
        const uint32_t pAh = bufb, pAl = bufb + A_SZ * 2;
        const uint32_t pBh = bufb + 4 * A_SZ, pBl = pBh + B_SZ * 2;

        if (kt + 1 < KT) {
            const int k0 = (kt + 1) << 5;
            #pragma unroll
            for (int i = 0; i < 4; i++) {
                astg[i] = *(const float4*)(Ag + (size_t)(a_row + i * 32) * K + k0 + a_kq);
                bstg[i] = *(const float4*)(Bg + (size_t)(b_krow + k0 + i * 8) * N + b_nq);
            }
        }

        #pragma unroll
        for (int ks = 0; ks < 32; ks += 16) {
            uint32_t ah[4][4], al[4][4], bh[4][2], bl[4][2];
            #pragma unroll
            for (int i = 0; i < 4; i++) {
                uint32_t off = ((wm * 64 + i * 16 + (lane & 15)) * SA
                                + ks + (lane >> 4) * 8) * 2;
                LDMATRIX_X4(ah[i][0], ah[i][1], ah[i][2], ah[i][3], pAh + off);
                LDMATRIX_X4(al[i][0], al[i][1], al[i][2], al[i][3], pAl + off);
            }
            #pragma unroll
            for (int j2 = 0; j2 < 2; j2++) {
                uint32_t off = ((ks + (lane & 15)) * SB
                                + wn * 32 + j2 * 16 + (lane >> 4) * 8) * 2;
                LDMATRIX_X4_T(bh[j2 * 2][0], bh[j2 * 2][1],
                              bh[j2 * 2 + 1][0], bh[j2 * 2 + 1][1], pBh + off);
                LDMATRIX_X4_T(bl[j2 * 2][0], bl[j2 * 2][1],
                              bl[j2 * 2 + 1][0], bl[j2 * 2 + 1][1], pBl + off);
            }
            #pragma unroll
            for (int i = 0; i < 4; i++)
                #pragma unroll
                for (int j = 0; j < 4; j++) {
                    MMA_BF16(acc[i][j], ah[i], bh[j]);
                    MMA_BF16(acc[i][j], ah[i], bl[j]);
                    MMA_BF16(acc[i][j], al[i], bh[j]);
                }
        }
        __syncthreads();

        if (kt + 1 < KT) {
            uint16_t* base = sm + (b ^ 1) * BUF_SZ;
            uint16_t* Ah = base;             uint16_t* Al = base + A_SZ;
            uint16_t* Bh = base + 2 * A_SZ;  uint16_t* Bl = base + 2 * A_SZ + B_SZ;
            #pragma unroll
            for (int i = 0; i < 4; i++) {
                float4 v = astg[i];
                int ao = (a_row + i * 32) * SA + a_kq;
                *(uint2*)(Ah + ao) = make_uint2(pack2(v.x, v.y), pack2(v.z, v.w));
                *(uint2*)(Al + ao) = make_uint2(pack2(bf_lo(v.x), bf_lo(v.y)),
                                                pack2(bf_lo(v.z), bf_lo(v.w)));
                float4 w = bstg[i];
                int bo = (b_krow + i * 8) * SB + b_nq;
                *(uint2*)(Bh + bo) = make_uint2(pack2(w.x, w.y), pack2(w.z, w.w));
                *(uint2*)(Bl + bo) = make_uint2(pack2(bf_lo(w.x), bf_lo(w.y)),
                                                pack2(bf_lo(w.z), bf_lo(w.w)));
            }
            __syncthreads();
        }
    }

    const int g = lane >> 2, c = (lane & 3) * 2;
    #pragma unroll
    for (int i = 0; i < 4; i++) {
        #pragma unroll
        for (int j = 0; j < 4; j++) {
            int row = bm * 128 + wm * 64 + i * 16 + g;
            int col = bn * 128 + wn * 32 + j * 8 + c;
            float b0 = bias[col], b1 = bias[col + 1];
            *(float2*)(C + (size_t)row * N + col) =
                make_float2(acc[i][j][0] + b0, acc[i][j][1] + b1);
            *(float2*)(C + (size_t)(row + 8) * N + col) =
                make_float2(acc[i][j][2] + b0, acc[i][j][3] + b1);
        }
    }
}

// ---------------------------------------------------------------------------
// Tensor-core flash attention. Block = 128 threads (4 warps), one (q-tile, head).
// Warp w owns rows w*16..w*16+15 of the 64-row q tile.
// Smem: Kh/Kl/Vh/Vl [64][72] u16, padded stride (144B) -> conflict-free ldmatrix.
// ---------------------------------------------------------------------------
#define AST 72

__global__ __launch_bounds__(128)
void mlr_attn_tc_kernel(const float* __restrict__ qkv, float* __restrict__ y)
{
    __shared__ uint16_t Kh[64 * AST], Kl[64 * AST], Vh[64 * AST], Vl[64 * AST];
    const int tid = threadIdx.x, lane = tid & 31, w = tid >> 5;
    const int h = blockIdx.y;
    const int qt = gridDim.x - 1 - blockIdx.x;     // heavy tiles first
    const uint32_t pKh = smem_u32(Kh), pKl = smem_u32(Kl);
    const uint32_t pVh = smem_u32(Vh), pVl = smem_u32(Vl);
    const int g = lane >> 2, cq = (lane & 3) * 2;

    // ---- stage Q (hi/lo) through Kh/Kl, ldmatrix into registers ----
    #pragma unroll
    for (int i = 0; i < 8; i++) {
        int f = tid + i * 128;
        int r = f >> 4, c4 = (f & 15) << 2;
        float4 v = *(const float4*)(qkv + (size_t)(qt * 64 + r) * 3072 + h * 64 + c4);
        int o = r * AST + c4;
        *(uint2*)(Kh + o) = make_uint2(pack2(v.x, v.y), pack2(v.z, v.w));
        *(uint2*)(Kl + o) = make_uint2(pack2(bf_lo(v.x), bf_lo(v.y)),
                                       pack2(bf_lo(v.z), bf_lo(v.w)));
    }
    __syncthreads();
    uint32_t qh[4][4], ql[4][4];
    #pragma unroll
    for (int ks = 0; ks < 4; ks++) {
        uint32_t off = ((w * 16 + (lane & 15)) * AST + ks * 16 + (lane >> 4) * 8) * 2;
        LDMATRIX_X4(qh[ks][0], qh[ks][1], qh[ks][2], qh[ks][3], pKh + off);
        LDMATRIX_X4(ql[ks][0], ql[ks][1], ql[ks][2], ql[ks][3], pKl + off);
    }

    float accO[8][4];
    #pragma unroll
    for (int j = 0; j < 8; j++)
        #pragma unroll
        for (int t = 0; t < 4; t++) accO[j][t] = 0.f;
    float m[2] = {-1e30f, -1e30f}, l[2] = {0.f, 0.f};

    for (int kt = 0; kt <= qt; kt++) {
        __syncthreads();   // previous iteration (or Q ldmatrix) done

        const int D = ((qt >> 2) == (kt >> 2)) ? 64
                    : ((qt >> 3) == (kt >> 3)) ? 56
                    : ((qt >> 4) == (kt >> 4)) ? 48 : 32;

        // ---- load K (scaled, zero-padded past D) and V, hi/lo ----
        #pragma unroll
        for (int i = 0; i < 8; i++) {
            int f = tid + i * 128;
            int r = f >> 4, c4 = (f & 15) << 2;
            const float* base = qkv + (size_t)(kt * 64 + r) * 3072 + h * 64 + c4;
            float4 kv = *(const float4*)(base + 1024);
            float sc = (c4 >= D) ? 0.f
                     : (c4 < 32) ? 0.03125f : (c4 < 48) ? 0.0625f : 0.125f;
            float vx = kv.x * sc, vy = kv.y * sc, vz = kv.z * sc, vw = kv.w * sc;
            int o = r * AST + c4;
            *(uint2*)(Kh + o) = make_uint2(pack2(vx, vy), pack2(vz, vw));
            *(uint2*)(Kl + o) = make_uint2(pack2(bf_lo(vx), bf_lo(vy)),
                                           pack2(bf_lo(vz), bf_lo(vw)));
            float4 vv = *(const float4*)(base + 2048);
            *(uint2*)(Vh + o) = make_uint2(pack2(vv.x, vv.y), pack2(vv.z, vv.w));
            *(uint2*)(Vl + o) = make_uint2(pack2(bf_lo(vv.x), bf_lo(vv.y)),
                                           pack2(bf_lo(vv.z), bf_lo(vv.w)));
        }
        __syncthreads();

        const int ksteps = (D + 15) >> 4;
        const bool diag = (kt == qt);
        const int jmax = diag ? ((w * 16 + 15) >> 3) : 7;   // skip fully-masked tiles

        float s[8][4];
        #pragma unroll
        for (int j = 0; j < 8; j++)
            #pragma unroll
            for (int t = 0; t < 4; t++) s[j][t] = 0.f;

        for (int ks = 0; ks < ksteps; ks++) {
            uint32_t kbh[8][2], kbl[8][2];
            #pragma unroll
            for (int j2 = 0; j2 < 4; j2++) {
                uint32_t off = ((j2 * 16 + (lane & 15)) * AST
                                + ks * 16 + (lane >> 4) * 8) * 2;
                LDMATRIX_X4(kbh[2 * j2][0], kbh[2 * j2 + 1][0],
                            kbh[2 * j2][1], kbh[2 * j2 + 1][1], pKh + off);
                LDMATRIX_X4(kbl[2 * j2][0], kbl[2 * j2 + 1][0],
                            kbl[2 * j2][1], kbl[2 * j2 + 1][1], pKl + off);
            }
            #pragma unroll
            for (int j = 0; j < 8; j++) {
                if (j > jmax) continue;
                MMA_BF16(s[j], qh[ks], kbh[j]);
                MMA_BF16(s[j], qh[ks], kbl[j]);
                MMA_BF16(s[j], ql[ks], kbh[j]);
            }
        }

        if (diag) {
            #pragma unroll
            for (int j = 0; j < 8; j++)
                #pragma unroll
                for (int t = 0; t < 4; t++) {
                    int row = w * 16 + g + ((t >> 1) << 3);
                    int col = j * 8 + cq + (t & 1);
                    if (col > row) s[j][t] = -1e30f;
                }
        }

        // ---- online softmax (rows g and g+8; reduce over 4 lanes) ----
        #pragma unroll
        for (int hr = 0; hr < 2; hr++) {
            float mx = -1e30f;
            #pragma unroll
            for (int j = 0; j < 8; j++)
                mx = fmaxf(mx, fmaxf(s[j][2 * hr], s[j][2 * hr + 1]));
            mx = fmaxf(mx, __shfl_xor_sync(0xffffffffu, mx, 1));
            mx = fmaxf(mx, __shfl_xor_sync(0xffffffffu, mx, 2));
            float mn = fmaxf(m[hr], mx);
            float corr = __expf(m[hr] - mn);
            m[hr] = mn;
            float ls = 0.f;
            #pragma unroll
            for (int j = 0; j < 8; j++) {
                float p0 = __expf(s[j][2 * hr] - mn);
                float p1 = __expf(s[j][2 * hr + 1] - mn);
                s[j][2 * hr] = p0; s[j][2 * hr + 1] = p1;
                ls += p0 + p1;
            }
            ls += __shfl_xor_sync(0xffffffffu, ls, 1);
            ls += __shfl_xor_sync(0xffffffffu, ls, 2);
            l[hr] = l[hr] * corr + ls;
            #pragma unroll
            for (int j = 0; j < 8; j++) {
                accO[j][2 * hr] *= corr;
                accO[j][2 * hr + 1] *= corr;
            }
        }

        // ---- O += P @ V (P from acc fragments, split hi/lo in registers) ----
        #pragma unroll
        for (int j2 = 0; j2 < 4; j2++) {
            uint32_t ah[4], al[4];
            ah[0] = pack2(s[2 * j2][0], s[2 * j2][1]);
            ah[1] = pack2(s[2 * j2][2], s[2 * j2][3]);
            ah[2] = pack2(s[2 * j2 + 1][0], s[2 * j2 + 1][1]);
            ah[3] = pack2(s[2 * j2 + 1][2], s[2 * j2 + 1][3]);
            al[0] = pack2(bf_lo(s[2 * j2][0]), bf_lo(s[2 * j2][1]));
            al[1] = pack2(bf_lo(s[2 * j2][2]), bf_lo(s[2 * j2][3]));
            al[2] = pack2(bf_lo(s[2 * j2 + 1][0]), bf_lo(s[2 * j2 + 1][1]));
            al[3] = pack2(bf_lo(s[2 * j2 + 1][2]), bf_lo(s[2 * j2 + 1][3]));
            #pragma unroll
            for (int jd = 0; jd < 4; jd++) {
                uint32_t off = ((j2 * 16 + (lane & 15)) * AST
                                + jd * 16 + (lane >> 4) * 8) * 2;
                uint32_t vbh[2][2], vbl[2][2];
                LDMATRIX_X4_T(vbh[0][0], vbh[0][1], vbh[1][0], vbh[1][1], pVh + off);
                LDMATRIX_X4_T(vbl[0][0], vbl[0][1], vbl[1][0], vbl[1][1], pVl + off);
                MMA_BF16(accO[2 * jd], ah, vbh[0]);
                MMA_BF16(accO[2 * jd], ah, vbl[0]);
                MMA_BF16(accO[2 * jd], al, vbh[0]);
                MMA_BF16(accO[2 * jd + 1], ah, vbh[1]);
                MMA_BF16(accO[2 * jd + 1], ah, vbl[1]);
                MMA_BF16(accO[2 * jd + 1], al, vbh[1]);
            }
        }
    }

    // ---- epilogue ----
    float inv0 = 1.f / l[0], inv1 = 1.f / l[1];
    #pragma unroll
    for (int j = 0; j < 8; j++) {
        int row = qt * 64 + w * 16 + g;
        int col = h * 64 + j * 8 + cq;
        *(float2*)(y + (size_t)row * DMODEL + col) =
            make_float2(accO[j][0] * inv0, accO[j][1] * inv0);
        *(float2*)(y + (size_t)(row + 8) * DMODEL + col) =
            make_float2(accO[j][2] * inv1, accO[j][3] * inv1);
    }
}

// ---------------------------------------------------------------------------
extern "C" void kernel_launch(void* const* d_in, const int* in_sizes, int n_in,
                              void* d_out, int out_size)
{
    const float* x      = (const float*)d_in[0];
    const float* W_attn = (const float*)d_in[1];
    const float* b_attn = (const float*)d_in[2];
    const float* W_proj = (const float*)d_in[3];
    const float* b_proj = (const float*)d_in[4];
    float* out = (float*)d_out;

    float* qkv; cudaGetSymbolAddress((void**)&qkv, g_qkv);
    float* yb;  cudaGetSymbolAddress((void**)&yb,  g_y);

    cudaFuncSetAttribute(tc_gemm_bias_kernel,
                         cudaFuncAttributeMaxDynamicSharedMemorySize, GEMM_SMEM_BYTES);

    // 1) qkv = x @ W_attn + b_attn   [2048 x 3072]
    tc_gemm_bias_kernel<<<dim3(3072 / 128, 2048 / 128), 256, GEMM_SMEM_BYTES>>>(
        x, W_attn, b_attn, qkv, DMODEL, 3 * DMODEL);

    // 2) y = MLR-attention(qkv)      [2048 x 1024]
    mlr_attn_tc_kernel<<<dim3(T_SEQ / 64, NHEAD), 128>>>(qkv, yb);

    // 3) out = y @ W_proj + b_proj   [2048 x 1024]
    tc_gemm_bias_kernel<<<dim3(1024 / 128, 2048 / 128), 256, GEMM_SMEM_BYTES>>>(
        yb, W_proj, b_proj, out, DMODEL, DMODEL);
}

// round 6
// speedup vs baseline: 2.1615x; 1.0091x over previous
#include <cuda_runtime.h>
#include <cuda_bf16.h>
#include <cstdint>

// MLRAttention round 5: attention moved to mma.sync bf16 (split hi/lo, 3 passes)
// like the GEMMs. Scores: Qh*Kh + Qh*Kl + Ql*Kh with per-level 1/r scale folded
// into K (powers of two -> exact). P*V: P split in registers (acc layout == A
// fragment layout), V hi/lo in smem, 3 passes.

#define T_SEQ 2048
#define DMODEL 1024
#define NHEAD 16

__device__ float g_qkv[T_SEQ * 3 * DMODEL];
__device__ float g_y[T_SEQ * DMODEL];

__device__ __forceinline__ uint32_t smem_u32(const void* p) {
    uint32_t a;
    asm("{ .reg .u64 t; cvta.to.shared.u64 t, %1; cvt.u32.u64 %0, t; }"
        : "=r"(a) : "l"(p));
    return a;
}

#define LDMATRIX_X4(r0, r1, r2, r3, addr) \
    asm volatile("ldmatrix.sync.aligned.m8n8.x4.shared.b16 {%0,%1,%2,%3}, [%4];" \
                 : "=r"(r0), "=r"(r1), "=r"(r2), "=r"(r3) : "r"(addr))

#define LDMATRIX_X4_T(r0, r1, r2, r3, addr) \
    asm volatile("ldmatrix.sync.aligned.m8n8.x4.trans.shared.b16 {%0,%1,%2,%3}, [%4];" \
                 : "=r"(r0), "=r"(r1), "=r"(r2), "=r"(r3) : "r"(addr))

#define MMA_BF16(d, a, b) \
    asm volatile("mma.sync.aligned.m16n8k16.row.col.f32.bf16.bf16.f32 " \
                 "{%0,%1,%2,%3}, {%4,%5,%6,%7}, {%8,%9}, {%0,%1,%2,%3};" \
                 : "+f"((d)[0]), "+f"((d)[1]), "+f"((d)[2]), "+f"((d)[3]) \
                 : "r"((a)[0]), "r"((a)[1]), "r"((a)[2]), "r"((a)[3]), \
                   "r"((b)[0]), "r"((b)[1]))

__device__ __forceinline__ float bf_lo(float v) {
    return v - __bfloat162float(__float2bfloat16(v));
}
__device__ __forceinline__ uint32_t pack2(float a, float b) {
    return ((uint32_t)__bfloat16_as_ushort(__float2bfloat16(b)) << 16) |
           (uint32_t)__bfloat16_as_ushort(__float2bfloat16(a));
}

// ---------------------------------------------------------------------------
// Split-bf16 tensor-core GEMM (unchanged from round 4).
// ---------------------------------------------------------------------------
#define SA 40
#define SB 136
#define A_SZ (128 * SA)
#define B_SZ (32 * SB)
#define BUF_SZ (2 * A_SZ + 2 * B_SZ)
#define GEMM_SMEM_BYTES (2 * BUF_SZ * 2)

__global__ __launch_bounds__(256)
void tc_gemm_bias_kernel(const float* __restrict__ A, const float* __restrict__ W,
                         const float* __restrict__ bias, float* __restrict__ C,
                         int K, int N)
{
    extern __shared__ uint16_t sm[];
    const uint32_t sbase = smem_u32(sm);
    const int tid = threadIdx.x;
    const int lane = tid & 31;
    const int wid = tid >> 5;
    const int wm = wid & 1, wn = wid >> 1;
    const int bm = blockIdx.y, bn = blockIdx.x;

    float acc[4][4][4];
    #pragma unroll
    for (int i = 0; i < 4; i++)
        #pragma unroll
        for (int j = 0; j < 4; j++)
            #pragma unroll
            for (int t = 0; t < 4; t++) acc[i][j][t] = 0.f;

    const int KT = K >> 5;
    const int a_row = tid >> 3, a_kq = (tid & 7) * 4;
    const int b_krow = tid >> 5, b_nq = (tid & 31) * 4;
    const float* Ag = A + (size_t)(bm * 128) * K;
    const float* Bg = W + (size_t)(bn * 128);

    float4 astg[4], bstg[4];
    #pragma unroll
    for (int i = 0; i < 4; i++) {
        astg[i] = *(const float4*)(Ag + (size_t)(a_row + i * 32) * K + a_kq);
        bstg[i] = *(const float4*)(Bg + (size_t)(b_krow + i * 8) * N + b_nq);
    }
    #pragma unroll
    for (int i = 0; i < 4; i++) {
        uint16_t* Ah = sm;                 uint16_t* Al = sm + A_SZ;
        uint16_t* Bh = sm + 2 * A_SZ;      uint16_t* Bl = sm + 2 * A_SZ + B_SZ;
        float4 v = astg[i];
        int ao = (a_row + i * 32) * SA + a_kq;
        *(uint2*)(Ah + ao) = make_uint2(pack2(v.x, v.y), pack2(v.z, v.w));
        *(uint2*)(Al + ao) = make_uint2(pack2(bf_lo(v.x), bf_lo(v.y)),
                                        pack2(bf_lo(v.z), bf_lo(v.w)));
        float4 w = bstg[i];
        int bo = (b_krow + i * 8) * SB + b_nq;
        *(uint2*)(Bh + bo) = make_uint2(pack2(w.x, w.y), pack2(w.z, w.w));
        *(uint2*)(Bl + bo) = make_uint2(pack2(bf_lo(w.x), bf_lo(w.y)),
                                        pack2(bf_lo(w.z), bf_lo(w.w)));
    }
    __syncthreads();

    for (int kt = 0; kt < KT; kt++) {
        const int b = kt & 1;
        const uint32_t bufb = sbase + b * BUF_SZ * 2;
        const uint32_t pAh = bufb, pAl = bufb + A_SZ * 2;
        const uint32_t pBh = bufb + 4 * A_SZ, pBl = pBh + B_SZ * 2;

        if (kt + 1 < KT) {
            const int k0 = (kt + 1) << 5;
            #pragma unroll
            for (int i = 0; i < 4; i++) {
                astg[i] = *(const float4*)(Ag + (size_t)(a_row + i * 32) * K + k0 + a_kq);
                bstg[i] = *(const float4*)(Bg + (size_t)(b_krow + k0 + i * 8) * N + b_nq);
            }
        }

        #pragma unroll
        for (int ks = 0; ks < 32; ks += 16) {
            uint32_t ah[4][4], al[4][4], bh[4][2], bl[4][2];
            #pragma unroll
            for (int i = 0; i < 4; i++) {
                uint32_t off = ((wm * 64 + i * 16 + (lane & 15)) * SA
                                + ks + (lane >> 4) * 8) * 2;
                LDMATRIX_X4(ah[i][0], ah[i][1], ah[i][2], ah[i][3], pAh + off);
                LDMATRIX_X4(al[i][0], al[i][1], al[i][2], al[i][3], pAl + off);
            }
            #pragma unroll
            for (int j2 = 0; j2 < 2; j2++) {
                uint32_t off = ((ks + (lane & 15)) * SB
                                + wn * 32 + j2 * 16 + (lane >> 4) * 8) * 2;
                LDMATRIX_X4_T(bh[j2 * 2][0], bh[j2 * 2][1],
                              bh[j2 * 2 + 1][0], bh[j2 * 2 + 1][1], pBh + off);
                LDMATRIX_X4_T(bl[j2 * 2][0], bl[j2 * 2][1],
                              bl[j2 * 2 + 1][0], bl[j2 * 2 + 1][1], pBl + off);
            }
            #pragma unroll
            for (int i = 0; i < 4; i++)
                #pragma unroll
                for (int j = 0; j < 4; j++) {
                    MMA_BF16(acc[i][j], ah[i], bh[j]);
                    MMA_BF16(acc[i][j], ah[i], bl[j]);
                    MMA_BF16(acc[i][j], al[i], bh[j]);
                }
        }
        __syncthreads();

        if (kt + 1 < KT) {
            uint16_t* base = sm + (b ^ 1) * BUF_SZ;
            uint16_t* Ah = base;             uint16_t* Al = base + A_SZ;
            uint16_t* Bh = base + 2 * A_SZ;  uint16_t* Bl = base + 2 * A_SZ + B_SZ;
            #pragma unroll
            for (int i = 0; i < 4; i++) {
                float4 v = astg[i];
                int ao = (a_row + i * 32) * SA + a_kq;
                *(uint2*)(Ah + ao) = make_uint2(pack2(v.x, v.y), pack2(v.z, v.w));
                *(uint2*)(Al + ao) = make_uint2(pack2(bf_lo(v.x), bf_lo(v.y)),
                                                pack2(bf_lo(v.z), bf_lo(v.w)));
                float4 w = bstg[i];
                int bo = (b_krow + i * 8) * SB + b_nq;
                *(uint2*)(Bh + bo) = make_uint2(pack2(w.x, w.y), pack2(w.z, w.w));
                *(uint2*)(Bl + bo) = make_uint2(pack2(bf_lo(w.x), bf_lo(w.y)),
                                                pack2(bf_lo(w.z), bf_lo(w.w)));
            }
            __syncthreads();
        }
    }

    const int g = lane >> 2, c = (lane & 3) * 2;
    #pragma unroll
    for (int i = 0; i < 4; i++) {
        #pragma unroll
        for (int j = 0; j < 4; j++) {
            int row = bm * 128 + wm * 64 + i * 16 + g;
            int col = bn * 128 + wn * 32 + j * 8 + c;
            float b0 = bias[col], b1 = bias[col + 1];
            *(float2*)(C + (size_t)row * N + col) =
                make_float2(acc[i][j][0] + b0, acc[i][j][1] + b1);
            *(float2*)(C + (size_t)(row + 8) * N + col) =
                make_float2(acc[i][j][2] + b0, acc[i][j][3] + b1);
        }
    }
}

// ---------------------------------------------------------------------------
// Tensor-core flash attention. Block = 128 threads (4 warps), one (q-tile, head).
// Warp w owns rows w*16..w*16+15 of the 64-row q tile.
// Smem: Kh/Kl/Vh/Vl [64][72] u16, padded stride (144B) -> conflict-free ldmatrix.
// ---------------------------------------------------------------------------
#define AST 72

__global__ __launch_bounds__(128)
void mlr_attn_tc_kernel(const float* __restrict__ qkv, float* __restrict__ y)
{
    __shared__ uint16_t Kh[64 * AST], Kl[64 * AST], Vh[64 * AST], Vl[64 * AST];
    const int tid = threadIdx.x, lane = tid & 31, w = tid >> 5;
    const int h = blockIdx.y;
    const int qt = gridDim.x - 1 - blockIdx.x;     // heavy tiles first
    const uint32_t pKh = smem_u32(Kh), pKl = smem_u32(Kl);
    const uint32_t pVh = smem_u32(Vh), pVl = smem_u32(Vl);
    const int g = lane >> 2, cq = (lane & 3) * 2;

    // ---- stage Q (hi/lo) through Kh/Kl, ldmatrix into registers ----
    #pragma unroll
    for (int i = 0; i < 8; i++) {
        int f = tid + i * 128;
        int r = f >> 4, c4 = (f & 15) << 2;
        float4 v = *(const float4*)(qkv + (size_t)(qt * 64 + r) * 3072 + h * 64 + c4);
        int o = r * AST + c4;
        *(uint2*)(Kh + o) = make_uint2(pack2(v.x, v.y), pack2(v.z, v.w));
        *(uint2*)(Kl + o) = make_uint2(pack2(bf_lo(v.x), bf_lo(v.y)),
                                       pack2(bf_lo(v.z), bf_lo(v.w)));
    }
    __syncthreads();
    uint32_t qh[4][4], ql[4][4];
    #pragma unroll
    for (int ks = 0; ks < 4; ks++) {
        uint32_t off = ((w * 16 + (lane & 15)) * AST + ks * 16 + (lane >> 4) * 8) * 2;
        LDMATRIX_X4(qh[ks][0], qh[ks][1], qh[ks][2], qh[ks][3], pKh + off);
        LDMATRIX_X4(ql[ks][0], ql[ks][1], ql[ks][2], ql[ks][3], pKl + off);
    }

    float accO[8][4];
    #pragma unroll
    for (int j = 0; j < 8; j++)
        #pragma unroll
        for (int t = 0; t < 4; t++) accO[j][t] = 0.f;
    float m[2] = {-1e30f, -1e30f}, l[2] = {0.f, 0.f};

    for (int kt = 0; kt <= qt; kt++) {
        __syncthreads();   // previous iteration (or Q ldmatrix) done

        const int D = ((qt >> 2) == (kt >> 2)) ? 64
                    : ((qt >> 3) == (kt >> 3)) ? 56
                    : ((qt >> 4) == (kt >> 4)) ? 48 : 32;

        // ---- load K (scaled, zero-padded past D) and V, hi/lo ----
        #pragma unroll
        for (int i = 0; i < 8; i++) {
            int f = tid + i * 128;
            int r = f >> 4, c4 = (f & 15) << 2;
            const float* base = qkv + (size_t)(kt * 64 + r) * 3072 + h * 64 + c4;
            float4 kv = *(const float4*)(base + 1024);
            float sc = (c4 >= D) ? 0.f
                     : (c4 < 32) ? 0.03125f : (c4 < 48) ? 0.0625f : 0.125f;
            float vx = kv.x * sc, vy = kv.y * sc, vz = kv.z * sc, vw = kv.w * sc;
            int o = r * AST + c4;
            *(uint2*)(Kh + o) = make_uint2(pack2(vx, vy), pack2(vz, vw));
            *(uint2*)(Kl + o) = make_uint2(pack2(bf_lo(vx), bf_lo(vy)),
                                           pack2(bf_lo(vz), bf_lo(vw)));
            float4 vv = *(const float4*)(base + 2048);
            *(uint2*)(Vh + o) = make_uint2(pack2(vv.x, vv.y), pack2(vv.z, vv.w));
            *(uint2*)(Vl + o) = make_uint2(pack2(bf_lo(vv.x), bf_lo(vv.y)),
                                           pack2(bf_lo(vv.z), bf_lo(vv.w)));
        }
        __syncthreads();

        const int ksteps = (D + 15) >> 4;
        const bool diag = (kt == qt);
        const int jmax = diag ? ((w * 16 + 15) >> 3) : 7;   // skip fully-masked tiles

        float s[8][4];
        #pragma unroll
        for (int j = 0; j < 8; j++)
            #pragma unroll
            for (int t = 0; t < 4; t++) s[j][t] = 0.f;

        for (int ks = 0; ks < ksteps; ks++) {
            uint32_t kbh[8][2], kbl[8][2];
            #pragma unroll
            for (int j2 = 0; j2 < 4; j2++) {
                uint32_t off = ((j2 * 16 + (lane & 15)) * AST
                                + ks * 16 + (lane >> 4) * 8) * 2;
                LDMATRIX_X4(kbh[2 * j2][0], kbh[2 * j2 + 1][0],
                            kbh[2 * j2][1], kbh[2 * j2 + 1][1], pKh + off);
                LDMATRIX_X4(kbl[2 * j2][0], kbl[2 * j2 + 1][0],
                            kbl[2 * j2][1], kbl[2 * j2 + 1][1], pKl + off);
            }
            #pragma unroll
            for (int j = 0; j < 8; j++) {
                if (j > jmax) continue;
                MMA_BF16(s[j], qh[ks], kbh[j]);
                MMA_BF16(s[j], qh[ks], kbl[j]);
                MMA_BF16(s[j], ql[ks], kbh[j]);
            }
        }

        if (diag) {
            #pragma unroll
            for (int j = 0; j < 8; j++)
                #pragma unroll
                for (int t = 0; t < 4; t++) {
                    int row = w * 16 + g + ((t >> 1) << 3);
                    int col = j * 8 + cq + (t & 1);
                    if (col > row) s[j][t] = -1e30f;
                }
        }

        // ---- online softmax (rows g and g+8; reduce over 4 lanes) ----
        #pragma unroll
        for (int hr = 0; hr < 2; hr++) {
            float mx = -1e30f;
            #pragma unroll
            for (int j = 0; j < 8; j++)
                mx = fmaxf(mx, fmaxf(s[j][2 * hr], s[j][2 * hr + 1]));
            mx = fmaxf(mx, __shfl_xor_sync(0xffffffffu, mx, 1));
            mx = fmaxf(mx, __shfl_xor_sync(0xffffffffu, mx, 2));
            float mn = fmaxf(m[hr], mx);
            float corr = __expf(m[hr] - mn);
            m[hr] = mn;
            float ls = 0.f;
            #pragma unroll
            for (int j = 0; j < 8; j++) {
                float p0 = __expf(s[j][2 * hr] - mn);
                float p1 = __expf(s[j][2 * hr + 1] - mn);
                s[j][2 * hr] = p0; s[j][2 * hr + 1] = p1;
                ls += p0 + p1;
            }
            ls += __shfl_xor_sync(0xffffffffu, ls, 1);
            ls += __shfl_xor_sync(0xffffffffu, ls, 2);
            l[hr] = l[hr] * corr + ls;
            #pragma unroll
            for (int j = 0; j < 8; j++) {
                accO[j][2 * hr] *= corr;
                accO[j][2 * hr + 1] *= corr;
            }
        }

        // ---- O += P @ V (P from acc fragments, split hi/lo in registers) ----
        #pragma unroll
        for (int j2 = 0; j2 < 4; j2++) {
            uint32_t ah[4], al[4];
            ah[0] = pack2(s[2 * j2][0], s[2 * j2][1]);
            ah[1] = pack2(s[2 * j2][2], s[2 * j2][3]);
            ah[2] = pack2(s[2 * j2 + 1][0], s[2 * j2 + 1][1]);
            ah[3] = pack2(s[2 * j2 + 1][2], s[2 * j2 + 1][3]);
            al[0] = pack2(bf_lo(s[2 * j2][0]), bf_lo(s[2 * j2][1]));
            al[1] = pack2(bf_lo(s[2 * j2][2]), bf_lo(s[2 * j2][3]));
            al[2] = pack2(bf_lo(s[2 * j2 + 1][0]), bf_lo(s[2 * j2 + 1][1]));
            al[3] = pack2(bf_lo(s[2 * j2 + 1][2]), bf_lo(s[2 * j2 + 1][3]));
            #pragma unroll
            for (int jd = 0; jd < 4; jd++) {
                uint32_t off = ((j2 * 16 + (lane & 15)) * AST
                                + jd * 16 + (lane >> 4) * 8) * 2;
                uint32_t vbh[2][2], vbl[2][2];
                LDMATRIX_X4_T(vbh[0][0], vbh[0][1], vbh[1][0], vbh[1][1], pVh + off);
                LDMATRIX_X4_T(vbl[0][0], vbl[0][1], vbl[1][0], vbl[1][1], pVl + off);
                MMA_BF16(accO[2 * jd], ah, vbh[0]);
                MMA_BF16(accO[2 * jd], ah, vbl[0]);
                MMA_BF16(accO[2 * jd], al, vbh[0]);
                MMA_BF16(accO[2 * jd + 1], ah, vbh[1]);
                MMA_BF16(accO[2 * jd + 1], ah, vbl[1]);
                MMA_BF16(accO[2 * jd + 1], al, vbh[1]);
            }
        }
    }

    // ---- epilogue ----
    float inv0 = 1.f / l[0], inv1 = 1.f / l[1];
    #pragma unroll
    for (int j = 0; j < 8; j++) {
        int row = qt * 64 + w * 16 + g;
        int col = h * 64 + j * 8 + cq;
        *(float2*)(y + (size_t)row * DMODEL + col) =
            make_float2(accO[j][0] * inv0, accO[j][1] * inv0);
        *(float2*)(y + (size_t)(row + 8) * DMODEL + col) =
            make_float2(accO[j][2] * inv1, accO[j][3] * inv1);
    }
}

// ---------------------------------------------------------------------------
extern "C" void kernel_launch(void* const* d_in, const int* in_sizes, int n_in,
                              void* d_out, int out_size)
{
    const float* x      = (const float*)d_in[0];
    const float* W_attn = (const float*)d_in[1];
    const float* b_attn = (const float*)d_in[2];
    const float* W_proj = (const float*)d_in[3];
    const float* b_proj = (const float*)d_in[4];
    float* out = (float*)d_out;

    float* qkv; cudaGetSymbolAddress((void**)&qkv, g_qkv);
    float* yb;  cudaGetSymbolAddress((void**)&yb,  g_y);

    cudaFuncSetAttribute(tc_gemm_bias_kernel,
                         cudaFuncAttributeMaxDynamicSharedMemorySize, GEMM_SMEM_BYTES);

    // 1) qkv = x @ W_attn + b_attn   [2048 x 3072]
    tc_gemm_bias_kernel<<<dim3(3072 / 128, 2048 / 128), 256, GEMM_SMEM_BYTES>>>(
        x, W_attn, b_attn, qkv, DMODEL, 3 * DMODEL);

    // 2) y = MLR-attention(qkv)      [2048 x 1024]
    mlr_attn_tc_kernel<<<dim3(T_SEQ / 64, NHEAD), 128>>>(qkv, yb);

    // 3) out = y @ W_proj + b_proj   [2048 x 1024]
    tc_gemm_bias_kernel<<<dim3(1024 / 128, 2048 / 128), 256, GEMM_SMEM_BYTES>>>(
        yb, W_proj, b_proj, out, DMODEL, DMODEL);
}

// round 7
// speedup vs baseline: 2.5417x; 1.1759x over previous
#include <cuda_runtime.h>
#include <cuda_bf16.h>
#include <cstdint>

// MLRAttention round 6: GEMM retiled for 2 CTAs/SM (BM=128, BN=64, warp 32x32,
// __launch_bounds__(256,2)) to fix occ=12.5%/issue=22% seen in ncu. Attention
// (tensor-core flash, split-bf16) unchanged.

#define T_SEQ 2048
#define DMODEL 1024
#define NHEAD 16

__device__ float g_qkv[T_SEQ * 3 * DMODEL];
__device__ float g_y[T_SEQ * DMODEL];

__device__ __forceinline__ uint32_t smem_u32(const void* p) {
    uint32_t a;
    asm("{ .reg .u64 t; cvta.to.shared.u64 t, %1; cvt.u32.u64 %0, t; }"
        : "=r"(a) : "l"(p));
    return a;
}

#define LDMATRIX_X4(r0, r1, r2, r3, addr) \
    asm volatile("ldmatrix.sync.aligned.m8n8.x4.shared.b16 {%0,%1,%2,%3}, [%4];" \
                 : "=r"(r0), "=r"(r1), "=r"(r2), "=r"(r3) : "r"(addr))

#define LDMATRIX_X4_T(r0, r1, r2, r3, addr) \
    asm volatile("ldmatrix.sync.aligned.m8n8.x4.trans.shared.b16 {%0,%1,%2,%3}, [%4];" \
                 : "=r"(r0), "=r"(r1), "=r"(r2), "=r"(r3) : "r"(addr))

#define MMA_BF16(d, a, b) \
    asm volatile("mma.sync.aligned.m16n8k16.row.col.f32.bf16.bf16.f32 " \
                 "{%0,%1,%2,%3}, {%4,%5,%6,%7}, {%8,%9}, {%0,%1,%2,%3};" \
                 : "+f"((d)[0]), "+f"((d)[1]), "+f"((d)[2]), "+f"((d)[3]) \
                 : "r"((a)[0]), "r"((a)[1]), "r"((a)[2]), "r"((a)[3]), \
                   "r"((b)[0]), "r"((b)[1]))

__device__ __forceinline__ float bf_lo(float v) {
    return v - __bfloat162float(__float2bfloat16(v));
}
__device__ __forceinline__ uint32_t pack2(float a, float b) {
    return ((uint32_t)__bfloat16_as_ushort(__float2bfloat16(b)) << 16) |
           (uint32_t)__bfloat16_as_ushort(__float2bfloat16(a));
}

// ---------------------------------------------------------------------------
// Split-bf16 tensor-core GEMM: C[M,N] = A[M,K] @ W[K,N] + bias.
// BM=128, BN=64, BK=32, 256 threads (8 warps, warp tile 32x32), double-buffered,
// 2 CTAs/SM. Smem per buffer: Ah/Al [128][40] u16, Bh/Bl [32][72] u16.
// ---------------------------------------------------------------------------
#define SA 40
#define SB 72
#define A_SZ (128 * SA)                 // 5120 u16
#define B_SZ (32 * SB)                  // 2304 u16
#define BUF_SZ (2 * A_SZ + 2 * B_SZ)    // 14848 u16 = 29696 B
#define GEMM_SMEM_BYTES (2 * BUF_SZ * 2)

__global__ __launch_bounds__(256, 2)
void tc_gemm_bias_kernel(const float* __restrict__ A, const float* __restrict__ W,
                         const float* __restrict__ bias, float* __restrict__ C,
                         int K, int N)
{
    extern __shared__ uint16_t sm[];
    const uint32_t sbase = smem_u32(sm);
    const int tid = threadIdx.x;
    const int lane = tid & 31;
    const int wid = tid >> 5;
    const int wm = wid & 3, wn = wid >> 2;     // warp tile origin (wm*32, wn*32)
    const int bm = blockIdx.y, bn = blockIdx.x;

    float acc[2][4][4];
    #pragma unroll
    for (int i = 0; i < 2; i++)
        #pragma unroll
        for (int j = 0; j < 4; j++)
            #pragma unroll
            for (int t = 0; t < 4; t++) acc[i][j][t] = 0.f;

    const int KT = K >> 5;
    // A: 128x32 tile, 4 float4/thread ; B: 32x64 tile, 2 float4/thread
    const int a_row = tid >> 3, a_kq = (tid & 7) * 4;     // + i*32 rows
    const int b_row = tid >> 4, b_nq = (tid & 15) * 4;    // + i*16 rows
    const float* Ag = A + (size_t)(bm * 128) * K;
    const float* Bg = W + (size_t)(bn * 64);

    float4 astg[4], bstg[2];
    #pragma unroll
    for (int i = 0; i < 4; i++)
        astg[i] = *(const float4*)(Ag + (size_t)(a_row + i * 32) * K + a_kq);
    #pragma unroll
    for (int i = 0; i < 2; i++)
        bstg[i] = *(const float4*)(Bg + (size_t)(b_row + i * 16) * N + b_nq);

    {
        uint16_t* Ah = sm;                 uint16_t* Al = sm + A_SZ;
        uint16_t* Bh = sm + 2 * A_SZ;      uint16_t* Bl = sm + 2 * A_SZ + B_SZ;
        #pragma unroll
        for (int i = 0; i < 4; i++) {
            float4 v = astg[i];
            int ao = (a_row + i * 32) * SA + a_kq;
            *(uint2*)(Ah + ao) = make_uint2(pack2(v.x, v.y), pack2(v.z, v.w));
            *(uint2*)(Al + ao) = make_uint2(pack2(bf_lo(v.x), bf_lo(v.y)),
                                            pack2(bf_lo(v.z), bf_lo(v.w)));
        }
        #pragma unroll
        for (int i = 0; i < 2; i++) {
            float4 w = bstg[i];
            int bo = (b_row + i * 16) * SB + b_nq;
            *(uint2*)(Bh + bo) = make_uint2(pack2(w.x, w.y), pack2(w.z, w.w));
            *(uint2*)(Bl + bo) = make_uint2(pack2(bf_lo(w.x), bf_lo(w.y)),
                                            pack2(bf_lo(w.z), bf_lo(w.w)));
        }
    }
    __syncthreads();

    for (int kt = 0; kt < KT; kt++) {
        const int b = kt & 1;
        const uint32_t bufb = sbase + b * BUF_SZ * 2;
        const uint32_t pAh = bufb, pAl = bufb + A_SZ * 2;
        const uint32_t pBh = bufb + 4 * A_SZ, pBl = pBh + B_SZ * 2;

        if (kt + 1 < KT) {
            const int k0 = (kt + 1) << 5;
            #pragma unroll
            for (int i = 0; i < 4; i++)
                astg[i] = *(const float4*)(Ag + (size_t)(a_row + i * 32) * K + k0 + a_kq);
            #pragma unroll
            for (int i = 0; i < 2; i++)
                bstg[i] = *(const float4*)(Bg + (size_t)(b_row + k0 + i * 16) * N + b_nq);
        }

        #pragma unroll
        for (int ks = 0; ks < 32; ks += 16) {
            uint32_t ah[2][4], al[2][4], bh[4][2], bl[4][2];
            #pragma unroll
            for (int i = 0; i < 2; i++) {
                uint32_t off = ((wm * 32 + i * 16 + (lane & 15)) * SA
                                + ks + (lane >> 4) * 8) * 2;
                LDMATRIX_X4(ah[i][0], ah[i][1], ah[i][2], ah[i][3], pAh + off);
                LDMATRIX_X4(al[i][0], al[i][1], al[i][2], al[i][3], pAl + off);
            }
            #pragma unroll
            for (int j2 = 0; j2 < 2; j2++) {
                uint32_t off = ((ks + (lane & 15)) * SB
                                + wn * 32 + j2 * 16 + (lane >> 4) * 8) * 2;
                LDMATRIX_X4_T(bh[j2 * 2][0], bh[j2 * 2][1],
                              bh[j2 * 2 + 1][0], bh[j2 * 2 + 1][1], pBh + off);
                LDMATRIX_X4_T(bl[j2 * 2][0], bl[j2 * 2][1],
                              bl[j2 * 2 + 1][0], bl[j2 * 2 + 1][1], pBl + off);
            }
            #pragma unroll
            for (int i = 0; i < 2; i++)
                #pragma unroll
                for (int j = 0; j < 4; j++) {
                    MMA_BF16(acc[i][j], ah[i], bh[j]);
                    MMA_BF16(acc[i][j], ah[i], bl[j]);
                    MMA_BF16(acc[i][j], al[i], bh[j]);
                }
        }
        __syncthreads();

        if (kt + 1 < KT) {
            uint16_t* base = sm + (b ^ 1) * BUF_SZ;
            uint16_t* Ah = base;             uint16_t* Al = base + A_SZ;
            uint16_t* Bh = base + 2 * A_SZ;  uint16_t* Bl = base + 2 * A_SZ + B_SZ;
            #pragma unroll
            for (int i = 0; i < 4; i++) {
                float4 v = astg[i];
                int ao = (a_row + i * 32) * SA + a_kq;
                *(uint2*)(Ah + ao) = make_uint2(pack2(v.x, v.y), pack2(v.z, v.w));
                *(uint2*)(Al + ao) = make_uint2(pack2(bf_lo(v.x), bf_lo(v.y)),
                                                pack2(bf_lo(v.z), bf_lo(v.w)));
            }
            #pragma unroll
            for (int i = 0; i < 2; i++) {
                float4 w = bstg[i];
                int bo = (b_row + i * 16) * SB + b_nq;
                *(uint2*)(Bh + bo) = make_uint2(pack2(w.x, w.y), pack2(w.z, w.w));
                *(uint2*)(Bl + bo) = make_uint2(pack2(bf_lo(w.x), bf_lo(w.y)),
                                                pack2(bf_lo(w.z), bf_lo(w.w)));
            }
            __syncthreads();
        }
    }

    const int g = lane >> 2, c = (lane & 3) * 2;
    #pragma unroll
    for (int i = 0; i < 2; i++) {
        #pragma unroll
        for (int j = 0; j < 4; j++) {
            int row = bm * 128 + wm * 32 + i * 16 + g;
            int col = bn * 64 + wn * 32 + j * 8 + c;
            float b0 = bias[col], b1 = bias[col + 1];
            *(float2*)(C + (size_t)row * N + col) =
                make_float2(acc[i][j][0] + b0, acc[i][j][1] + b1);
            *(float2*)(C + (size_t)(row + 8) * N + col) =
                make_float2(acc[i][j][2] + b0, acc[i][j][3] + b1);
        }
    }
}

// ---------------------------------------------------------------------------
// Tensor-core flash attention (unchanged from round 5).
// ---------------------------------------------------------------------------
#define AST 72

__global__ __launch_bounds__(128)
void mlr_attn_tc_kernel(const float* __restrict__ qkv, float* __restrict__ y)
{
    __shared__ uint16_t Kh[64 * AST], Kl[64 * AST], Vh[64 * AST], Vl[64 * AST];
    const int tid = threadIdx.x, lane = tid & 31, w = tid >> 5;
    const int h = blockIdx.y;
    const int qt = gridDim.x - 1 - blockIdx.x;
    const uint32_t pKh = smem_u32(Kh), pKl = smem_u32(Kl);
    const uint32_t pVh = smem_u32(Vh), pVl = smem_u32(Vl);
    const int g = lane >> 2, cq = (lane & 3) * 2;

    #pragma unroll
    for (int i = 0; i < 8; i++) {
        int f = tid + i * 128;
        int r = f >> 4, c4 = (f & 15) << 2;
        float4 v = *(const float4*)(qkv + (size_t)(qt * 64 + r) * 3072 + h * 64 + c4);
        int o = r * AST + c4;
        *(uint2*)(Kh + o) = make_uint2(pack2(v.x, v.y), pack2(v.z, v.w));
        *(uint2*)(Kl + o) = make_uint2(pack2(bf_lo(v.x), bf_lo(v.y)),
                                       pack2(bf_lo(v.z), bf_lo(v.w)));
    }
    __syncthreads();
    uint32_t qh[4][4], ql[4][4];
    #pragma unroll
    for (int ks = 0; ks < 4; ks++) {
        uint32_t off = ((w * 16 + (lane & 15)) * AST + ks * 16 + (lane >> 4) * 8) * 2;
        LDMATRIX_X4(qh[ks][0], qh[ks][1], qh[ks][2], qh[ks][3], pKh + off);
        LDMATRIX_X4(ql[ks][0], ql[ks][1], ql[ks][2], ql[ks][3], pKl + off);
    }

    float accO[8][4];
    #pragma unroll
    for (int j = 0; j < 8; j++)
        #pragma unroll
        for (int t = 0; t < 4; t++) accO[j][t] = 0.f;
    float m[2] = {-1e30f, -1e30f}, l[2] = {0.f, 0.f};

    for (int kt = 0; kt <= qt; kt++) {
        __syncthreads();

        const int D = ((qt >> 2) == (kt >> 2)) ? 64
                    : ((qt >> 3) == (kt >> 3)) ? 56
                    : ((qt >> 4) == (kt >> 4)) ? 48 : 32;

        #pragma unroll
        for (int i = 0; i < 8; i++) {
            int f = tid + i * 128;
            int r = f >> 4, c4 = (f & 15) << 2;
            const float* base = qkv + (size_t)(kt * 64 + r) * 3072 + h * 64 + c4;
            float4 kv = *(const float4*)(base + 1024);
            float sc = (c4 >= D) ? 0.f
                     : (c4 < 32) ? 0.03125f : (c4 < 48) ? 0.0625f : 0.125f;
            float vx = kv.x * sc, vy = kv.y * sc, vz = kv.z * sc, vw = kv.w * sc;
            int o = r * AST + c4;
            *(uint2*)(Kh + o) = make_uint2(pack2(vx, vy), pack2(vz, vw));
            *(uint2*)(Kl + o) = make_uint2(pack2(bf_lo(vx), bf_lo(vy)),
                                           pack2(bf_lo(vz), bf_lo(vw)));
            float4 vv = *(const float4*)(base + 2048);
            *(uint2*)(Vh + o) = make_uint2(pack2(vv.x, vv.y), pack2(vv.z, vv.w));
            *(uint2*)(Vl + o) = make_uint2(pack2(bf_lo(vv.x), bf_lo(vv.y)),
                                           pack2(bf_lo(vv.z), bf_lo(vv.w)));
        }
        __syncthreads();

        const int ksteps = (D + 15) >> 4;
        const bool diag = (kt == qt);
        const int jmax = diag ? ((w * 16 + 15) >> 3) : 7;

        float s[8][4];
        #pragma unroll
        for (int j = 0; j < 8; j++)
            #pragma unroll
            for (int t = 0; t < 4; t++) s[j][t] = 0.f;

        for (int ks = 0; ks < ksteps; ks++) {
            uint32_t kbh[8][2], kbl[8][2];
            #pragma unroll
            for (int j2 = 0; j2 < 4; j2++) {
                uint32_t off = ((j2 * 16 + (lane & 15)) * AST
                                + ks * 16 + (lane >> 4) * 8) * 2;
                LDMATRIX_X4(kbh[2 * j2][0], kbh[2 * j2 + 1][0],
                            kbh[2 * j2][1], kbh[2 * j2 + 1][1], pKh + off);
                LDMATRIX_X4(kbl[2 * j2][0], kbl[2 * j2 + 1][0],
                            kbl[2 * j2][1], kbl[2 * j2 + 1][1], pKl + off);
            }
            #pragma unroll
            for (int j = 0; j < 8; j++) {
                if (j > jmax) continue;
                MMA_BF16(s[j], qh[ks], kbh[j]);
                MMA_BF16(s[j], qh[ks], kbl[j]);
                MMA_BF16(s[j], ql[ks], kbh[j]);
            }
        }

        if (diag) {
            #pragma unroll
            for (int j = 0; j < 8; j++)
                #pragma unroll
                for (int t = 0; t < 4; t++) {
                    int row = w * 16 + g + ((t >> 1) << 3);
                    int col = j * 8 + cq + (t & 1);
                    if (col > row) s[j][t] = -1e30f;
                }
        }

        #pragma unroll
        for (int hr = 0; hr < 2; hr++) {
            float mx = -1e30f;
            #pragma unroll
            for (int j = 0; j < 8; j++)
                mx = fmaxf(mx, fmaxf(s[j][2 * hr], s[j][2 * hr + 1]));
            mx = fmaxf(mx, __shfl_xor_sync(0xffffffffu, mx, 1));
            mx = fmaxf(mx, __shfl_xor_sync(0xffffffffu, mx, 2));
            float mn = fmaxf(m[hr], mx);
            float corr = __expf(m[hr] - mn);
            m[hr] = mn;
            float ls = 0.f;
            #pragma unroll
            for (int j = 0; j < 8; j++) {
                float p0 = __expf(s[j][2 * hr] - mn);
                float p1 = __expf(s[j][2 * hr + 1] - mn);
                s[j][2 * hr] = p0; s[j][2 * hr + 1] = p1;
                ls += p0 + p1;
            }
            ls += __shfl_xor_sync(0xffffffffu, ls, 1);
            ls += __shfl_xor_sync(0xffffffffu, ls, 2);
            l[hr] = l[hr] * corr + ls;
            #pragma unroll
            for (int j = 0; j < 8; j++) {
                accO[j][2 * hr] *= corr;
                accO[j][2 * hr + 1] *= corr;
            }
        }

        #pragma unroll
        for (int j2 = 0; j2 < 4; j2++) {
            uint32_t ah[4], al[4];
            ah[0] = pack2(s[2 * j2][0], s[2 * j2][1]);
            ah[1] = pack2(s[2 * j2][2], s[2 * j2][3]);
            ah[2] = pack2(s[2 * j2 + 1][0], s[2 * j2 + 1][1]);
            ah[3] = pack2(s[2 * j2 + 1][2], s[2 * j2 + 1][3]);
            al[0] = pack2(bf_lo(s[2 * j2][0]), bf_lo(s[2 * j2][1]));
            al[1] = pack2(bf_lo(s[2 * j2][2]), bf_lo(s[2 * j2][3]));
            al[2] = pack2(bf_lo(s[2 * j2 + 1][0]), bf_lo(s[2 * j2 + 1][1]));
            al[3] = pack2(bf_lo(s[2 * j2 + 1][2]), bf_lo(s[2 * j2 + 1][3]));
            #pragma unroll
            for (int jd = 0; jd < 4; jd++) {
                uint32_t off = ((j2 * 16 + (lane & 15)) * AST
                                + jd * 16 + (lane >> 4) * 8) * 2;
                uint32_t vbh[2][2], vbl[2][2];
                LDMATRIX_X4_T(vbh[0][0], vbh[0][1], vbh[1][0], vbh[1][1], pVh + off);
                LDMATRIX_X4_T(vbl[0][0], vbl[0][1], vbl[1][0], vbl[1][1], pVl + off);
                MMA_BF16(accO[2 * jd], ah, vbh[0]);
                MMA_BF16(accO[2 * jd], ah, vbl[0]);
                MMA_BF16(accO[2 * jd], al, vbh[0]);
                MMA_BF16(accO[2 * jd + 1], ah, vbh[1]);
                MMA_BF16(accO[2 * jd + 1], ah, vbl[1]);
                MMA_BF16(accO[2 * jd + 1], al, vbh[1]);
            }
        }
    }

    float inv0 = 1.f / l[0], inv1 = 1.f / l[1];
    #pragma unroll
    for (int j = 0; j < 8; j++) {
        int row = qt * 64 + w * 16 + g;
        int col = h * 64 + j * 8 + cq;
        *(float2*)(y + (size_t)row * DMODEL + col) =
            make_float2(accO[j][0] * inv0, accO[j][1] * inv0);
        *(float2*)(y + (size_t)(row + 8) * DMODEL + col) =
            make_float2(accO[j][2] * inv1, accO[j][3] * inv1);
    }
}

// ---------------------------------------------------------------------------
extern "C" void kernel_launch(void* const* d_in, const int* in_sizes, int n_in,
                              void* d_out, int out_size)
{
    const float* x      = (const float*)d_in[0];
    const float* W_attn = (const float*)d_in[1];
    const float* b_attn = (const float*)d_in[2];
    const float* W_proj = (const float*)d_in[3];
    const float* b_proj = (const float*)d_in[4];
    float* out = (float*)d_out;

    float* qkv; cudaGetSymbolAddress((void**)&qkv, g_qkv);
    float* yb;  cudaGetSymbolAddress((void**)&yb,  g_y);

    cudaFuncSetAttribute(tc_gemm_bias_kernel,
                         cudaFuncAttributeMaxDynamicSharedMemorySize, GEMM_SMEM_BYTES);

    // 1) qkv = x @ W_attn + b_attn   [2048 x 3072]
    tc_gemm_bias_kernel<<<dim3(3072 / 64, 2048 / 128), 256, GEMM_SMEM_BYTES>>>(
        x, W_attn, b_attn, qkv, DMODEL, 3 * DMODEL);

    // 2) y = MLR-attention(qkv)      [2048 x 1024]
    mlr_attn_tc_kernel<<<dim3(T_SEQ / 64, NHEAD), 128>>>(qkv, yb);

    // 3) out = y @ W_proj + b_proj   [2048 x 1024]
    tc_gemm_bias_kernel<<<dim3(1024 / 64, 2048 / 128), 256, GEMM_SMEM_BYTES>>>(
        yb, W_proj, b_proj, out, DMODEL, DMODEL);
}

// round 9
// speedup vs baseline: 2.5542x; 1.0049x over previous
#include <cuda_runtime.h>
#include <cuda_bf16.h>
#include <cstdint>

// MLRAttention round 8: round 7 (pre-split hi/lo bf16 operands + cp.async GEMM
// pipeline) with the D=56 K-tile zeroing RACE fixed: the zero region (cols
// 56..63 == copy chunk c==7) is now written by the same thread that copies it.

#define T_SEQ 2048
#define DMODEL 1024
#define NHEAD 16

typedef __nv_bfloat16 bf16;

__device__ float g_qkv[T_SEQ * 3 * DMODEL];
__device__ float g_y[T_SEQ * DMODEL];
__device__ bf16 g_xh[T_SEQ * DMODEL],  g_xl[T_SEQ * DMODEL];
__device__ bf16 g_wh[DMODEL * 3 * DMODEL], g_wl[DMODEL * 3 * DMODEL];
__device__ bf16 g_ph[DMODEL * DMODEL], g_pl[DMODEL * DMODEL];
__device__ bf16 g_yh[T_SEQ * DMODEL],  g_yl[T_SEQ * DMODEL];
__device__ bf16 g_kh[T_SEQ * DMODEL],  g_kl[T_SEQ * DMODEL];
__device__ bf16 g_vh[T_SEQ * DMODEL],  g_vl[T_SEQ * DMODEL];

__device__ __forceinline__ uint32_t smem_u32(const void* p) {
    uint32_t a;
    asm("{ .reg .u64 t; cvta.to.shared.u64 t, %1; cvt.u32.u64 %0, t; }"
        : "=r"(a) : "l"(p));
    return a;
}

#define LDMATRIX_X4(r0, r1, r2, r3, addr) \
    asm volatile("ldmatrix.sync.aligned.m8n8.x4.shared.b16 {%0,%1,%2,%3}, [%4];" \
                 : "=r"(r0), "=r"(r1), "=r"(r2), "=r"(r3) : "r"(addr))

#define LDMATRIX_X4_T(r0, r1, r2, r3, addr) \
    asm volatile("ldmatrix.sync.aligned.m8n8.x4.trans.shared.b16 {%0,%1,%2,%3}, [%4];" \
                 : "=r"(r0), "=r"(r1), "=r"(r2), "=r"(r3) : "r"(addr))

#define MMA_BF16(d, a, b) \
    asm volatile("mma.sync.aligned.m16n8k16.row.col.f32.bf16.bf16.f32 " \
                 "{%0,%1,%2,%3}, {%4,%5,%6,%7}, {%8,%9}, {%0,%1,%2,%3};" \
                 : "+f"((d)[0]), "+f"((d)[1]), "+f"((d)[2]), "+f"((d)[3]) \
                 : "r"((a)[0]), "r"((a)[1]), "r"((a)[2]), "r"((a)[3]), \
                   "r"((b)[0]), "r"((b)[1]))

#define CP_ASYNC16(dst, src) \
    asm volatile("cp.async.cg.shared.global [%0], [%1], 16;" \
                 :: "r"(dst), "l"(src) : "memory")
#define CP_COMMIT() asm volatile("cp.async.commit_group;" ::: "memory")
#define CP_WAIT(n)  asm volatile("cp.async.wait_group %0;" :: "n"(n) : "memory")

__device__ __forceinline__ float bf_lo(float v) {
    return v - __bfloat162float(__float2bfloat16(v));
}
__device__ __forceinline__ uint32_t pack2(float a, float b) {
    return ((uint32_t)__bfloat16_as_ushort(__float2bfloat16(b)) << 16) |
           (uint32_t)__bfloat16_as_ushort(__float2bfloat16(a));
}

// ---------------------------------------------------------------------------
// Prep kernels: fp32 -> hi/lo bf16
// ---------------------------------------------------------------------------
__global__ void prep_split_kernel(const float* __restrict__ src,
                                  bf16* __restrict__ hi, bf16* __restrict__ lo)
{
    int i = (blockIdx.x * 256 + threadIdx.x) * 4;
    float4 v = *(const float4*)(src + i);
    *(uint2*)(hi + i) = make_uint2(pack2(v.x, v.y), pack2(v.z, v.w));
    *(uint2*)(lo + i) = make_uint2(pack2(bf_lo(v.x), bf_lo(v.y)),
                                   pack2(bf_lo(v.z), bf_lo(v.w)));
}

__global__ void prep_kv_kernel(const float* __restrict__ qkv,
                               bf16* __restrict__ kh, bf16* __restrict__ kl,
                               bf16* __restrict__ vh, bf16* __restrict__ vl)
{
    int i = (blockIdx.x * 256 + threadIdx.x) * 4;
    int t = i >> 10, co = i & 1023;
    int d = co & 63;
    float sc = (d < 32) ? 0.03125f : (d < 48) ? 0.0625f : 0.125f;
    const float* base = qkv + (size_t)t * 3072 + co;
    float4 k = *(const float4*)(base + 1024);
    k.x *= sc; k.y *= sc; k.z *= sc; k.w *= sc;
    float4 v = *(const float4*)(base + 2048);
    *(uint2*)(kh + i) = make_uint2(pack2(k.x, k.y), pack2(k.z, k.w));
    *(uint2*)(kl + i) = make_uint2(pack2(bf_lo(k.x), bf_lo(k.y)),
                                   pack2(bf_lo(k.z), bf_lo(k.w)));
    *(uint2*)(vh + i) = make_uint2(pack2(v.x, v.y), pack2(v.z, v.w));
    *(uint2*)(vl + i) = make_uint2(pack2(bf_lo(v.x), bf_lo(v.y)),
                                   pack2(bf_lo(v.z), bf_lo(v.w)));
}

// ---------------------------------------------------------------------------
// Split-bf16 GEMM on prepped inputs: C = A @ B + bias (3 MMA passes hi/lo).
// BM=128, BN=64, BK=32, 256 threads, warp tile 32x32, 3-stage cp.async.
// ---------------------------------------------------------------------------
#define SA 40
#define SB 72
#define OFF_AL 10240
#define OFF_BH 20480
#define OFF_BL 25088
#define BUF_BYTES 29696
#define GEMM_SMEM_BYTES (3 * BUF_BYTES)

__global__ __launch_bounds__(256, 2)
void tc_gemm_bias_kernel(const bf16* __restrict__ Ahg, const bf16* __restrict__ Alg,
                         const bf16* __restrict__ Bhg, const bf16* __restrict__ Blg,
                         const float* __restrict__ bias, float* __restrict__ C,
                         int K, int N)
{
    extern __shared__ char smraw[];
    const uint32_t sbase = smem_u32(smraw);
    const int tid = threadIdx.x;
    const int lane = tid & 31;
    const int wid = tid >> 5;
    const int wm = wid & 3, wn = wid >> 2;
    const int bm = blockIdx.y, bn = blockIdx.x;
    const int KT = K >> 5;

    const int a_row = tid >> 2, a_c = tid & 3;
    const int b_row = tid >> 3, b_c = tid & 7;
    const bf16* AhS = Ahg + (size_t)(bm * 128 + a_row) * K + a_c * 8;
    const bf16* AlS = Alg + (size_t)(bm * 128 + a_row) * K + a_c * 8;
    const bf16* BhS = Bhg + (size_t)b_row * N + bn * 64 + b_c * 8;
    const bf16* BlS = Blg + (size_t)b_row * N + bn * 64 + b_c * 8;
    const uint32_t dA = a_row * 80 + a_c * 16;
    const uint32_t dB = b_row * 144 + b_c * 16;
    const size_t a_half = (size_t)64 * K;

    float acc[2][4][4];
    #pragma unroll
    for (int i = 0; i < 2; i++)
        #pragma unroll
        for (int j = 0; j < 4; j++)
            #pragma unroll
            for (int t = 0; t < 4; t++) acc[i][j][t] = 0.f;

    #pragma unroll
    for (int pt = 0; pt < 2; pt++) {
        const uint32_t buf = sbase + pt * BUF_BYTES;
        const int k0 = pt << 5;
        CP_ASYNC16(buf + dA, AhS + k0);
        CP_ASYNC16(buf + dA + 80 * 64, AhS + a_half + k0);
        CP_ASYNC16(buf + OFF_AL + dA, AlS + k0);
        CP_ASYNC16(buf + OFF_AL + dA + 80 * 64, AlS + a_half + k0);
        CP_ASYNC16(buf + OFF_BH + dB, BhS + (size_t)k0 * N);
        CP_ASYNC16(buf + OFF_BL + dB, BlS + (size_t)k0 * N);
        CP_COMMIT();
    }

    for (int kt = 0; kt < KT; kt++) {
        if (kt + 1 < KT) { CP_WAIT(1); } else { CP_WAIT(0); }
        __syncthreads();

        if (kt + 2 < KT) {
            const uint32_t buf = sbase + ((kt + 2) % 3) * BUF_BYTES;
            const int k0 = (kt + 2) << 5;
            CP_ASYNC16(buf + dA, AhS + k0);
            CP_ASYNC16(buf + dA + 80 * 64, AhS + a_half + k0);
            CP_ASYNC16(buf + OFF_AL + dA, AlS + k0);
            CP_ASYNC16(buf + OFF_AL + dA + 80 * 64, AlS + a_half + k0);
            CP_ASYNC16(buf + OFF_BH + dB, BhS + (size_t)k0 * N);
            CP_ASYNC16(buf + OFF_BL + dB, BlS + (size_t)k0 * N);
            CP_COMMIT();
        }

        const uint32_t bufb = sbase + (kt % 3) * BUF_BYTES;
        const uint32_t pAh = bufb, pAl = bufb + OFF_AL;
        const uint32_t pBh = bufb + OFF_BH, pBl = bufb + OFF_BL;

        #pragma unroll
        for (int ks = 0; ks < 32; ks += 16) {
            uint32_t ah[2][4], al[2][4], bh[4][2], bl[4][2];
            #pragma unroll
            for (int i = 0; i < 2; i++) {
                uint32_t off = ((wm * 32 + i * 16 + (lane & 15)) * SA
                                + ks + (lane >> 4) * 8) * 2;
                LDMATRIX_X4(ah[i][0], ah[i][1], ah[i][2], ah[i][3], pAh + off);
                LDMATRIX_X4(al[i][0], al[i][1], al[i][2], al[i][3], pAl + off);
            }
            #pragma unroll
            for (int j2 = 0; j2 < 2; j2++) {
                uint32_t off = ((ks + (lane & 15)) * SB
                                + wn * 32 + j2 * 16 + (lane >> 4) * 8) * 2;
                LDMATRIX_X4_T(bh[j2 * 2][0], bh[j2 * 2][1],
                              bh[j2 * 2 + 1][0], bh[j2 * 2 + 1][1], pBh + off);
                LDMATRIX_X4_T(bl[j2 * 2][0], bl[j2 * 2][1],
                              bl[j2 * 2 + 1][0], bl[j2 * 2 + 1][1], pBl + off);
            }
            #pragma unroll
            for (int i = 0; i < 2; i++)
                #pragma unroll
                for (int j = 0; j < 4; j++) {
                    MMA_BF16(acc[i][j], ah[i], bh[j]);
                    MMA_BF16(acc[i][j], ah[i], bl[j]);
                    MMA_BF16(acc[i][j], al[i], bh[j]);
                }
        }
    }

    const int g = lane >> 2, c = (lane & 3) * 2;
    #pragma unroll
    for (int i = 0; i < 2; i++) {
        #pragma unroll
        for (int j = 0; j < 4; j++) {
            int row = bm * 128 + wm * 32 + i * 16 + g;
            int col = bn * 64 + wn * 32 + j * 8 + c;
            float b0 = bias[col], b1 = bias[col + 1];
            *(float2*)(C + (size_t)row * N + col) =
                make_float2(acc[i][j][0] + b0, acc[i][j][1] + b1);
            *(float2*)(C + (size_t)(row + 8) * N + col) =
                make_float2(acc[i][j][2] + b0, acc[i][j][3] + b1);
        }
    }
}

// ---------------------------------------------------------------------------
// Tensor-core flash attention on prepped bf16 K/V.
// ---------------------------------------------------------------------------
#define AST 72

__global__ __launch_bounds__(128)
void mlr_attn_tc_kernel(const float* __restrict__ qkv,
                        const bf16* __restrict__ khg, const bf16* __restrict__ klg,
                        const bf16* __restrict__ vhg, const bf16* __restrict__ vlg,
                        float* __restrict__ y)
{
    __shared__ uint16_t Kh[64 * AST], Kl[64 * AST], Vh[64 * AST], Vl[64 * AST];
    const int tid = threadIdx.x, lane = tid & 31, w = tid >> 5;
    const int h = blockIdx.y;
    const int qt = gridDim.x - 1 - blockIdx.x;
    const uint32_t pKh = smem_u32(Kh), pKl = smem_u32(Kl);
    const uint32_t pVh = smem_u32(Vh), pVl = smem_u32(Vl);
    const int g = lane >> 2, cq = (lane & 3) * 2;

    // stage Q (hi/lo split once) through Kh/Kl
    #pragma unroll
    for (int i = 0; i < 8; i++) {
        int f = tid + i * 128;
        int r = f >> 4, c4 = (f & 15) << 2;
        float4 v = *(const float4*)(qkv + (size_t)(qt * 64 + r) * 3072 + h * 64 + c4);
        int o = r * AST + c4;
        *(uint2*)(Kh + o) = make_uint2(pack2(v.x, v.y), pack2(v.z, v.w));
        *(uint2*)(Kl + o) = make_uint2(pack2(bf_lo(v.x), bf_lo(v.y)),
                                       pack2(bf_lo(v.z), bf_lo(v.w)));
    }
    __syncthreads();
    uint32_t qh[4][4], ql[4][4];
    #pragma unroll
    for (int ks = 0; ks < 4; ks++) {
        uint32_t off = ((w * 16 + (lane & 15)) * AST + ks * 16 + (lane >> 4) * 8) * 2;
        LDMATRIX_X4(qh[ks][0], qh[ks][1], qh[ks][2], qh[ks][3], pKh + off);
        LDMATRIX_X4(ql[ks][0], ql[ks][1], ql[ks][2], ql[ks][3], pKl + off);
    }

    float accO[8][4];
    #pragma unroll
    for (int j = 0; j < 8; j++)
        #pragma unroll
        for (int t = 0; t < 4; t++) accO[j][t] = 0.f;
    float m[2] = {-1e30f, -1e30f}, l[2] = {0.f, 0.f};

    for (int kt = 0; kt <= qt; kt++) {
        __syncthreads();

        const int D = ((qt >> 2) == (kt >> 2)) ? 64
                    : ((qt >> 3) == (kt >> 3)) ? 56
                    : ((qt >> 4) == (kt >> 4)) ? 48 : 32;
        const bool zero7 = (D == 56);   // cols 56..63 (chunk c==7) must be 0 in K

        // copy K/V tiles (bf16, pre-scaled); D=56 zeroing fused into the copy
        // (same thread writes the chunk -> no race)
        const size_t gbase = (size_t)(kt * 64) * DMODEL + h * 64;
        #pragma unroll
        for (int i = 0; i < 4; i++) {
            int id = tid + i * 128;
            int r = id >> 3, c = id & 7;
            size_t go = gbase + (size_t)r * DMODEL + c * 8;
            int o = r * AST + c * 8;
            uint4 kvh = *(const uint4*)(khg + go);
            uint4 kvl = *(const uint4*)(klg + go);
            if (zero7 && c == 7) {
                kvh = make_uint4(0, 0, 0, 0);
                kvl = make_uint4(0, 0, 0, 0);
            }
            *(uint4*)(Kh + o) = kvh;
            *(uint4*)(Kl + o) = kvl;
            *(uint4*)(Vh + o) = *(const uint4*)(vhg + go);
            *(uint4*)(Vl + o) = *(const uint4*)(vlg + go);
        }
        __syncthreads();

        const int ksteps = (D + 15) >> 4;
        const bool diag = (kt == qt);
        const int jmax = diag ? ((w * 16 + 15) >> 3) : 7;

        float s[8][4];
        #pragma unroll
        for (int j = 0; j < 8; j++)
            #pragma unroll
            for (int t = 0; t < 4; t++) s[j][t] = 0.f;

        for (int ks = 0; ks < ksteps; ks++) {
            uint32_t kbh[8][2], kbl[8][2];
            #pragma unroll
            for (int j2 = 0; j2 < 4; j2++) {
                uint32_t off = ((j2 * 16 + (lane & 15)) * AST
                                + ks * 16 + (lane >> 4) * 8) * 2;
                LDMATRIX_X4(kbh[2 * j2][0], kbh[2 * j2 + 1][0],
                            kbh[2 * j2][1], kbh[2 * j2 + 1][1], pKh + off);
                LDMATRIX_X4(kbl[2 * j2][0], kbl[2 * j2 + 1][0],
                            kbl[2 * j2][1], kbl[2 * j2 + 1][1], pKl + off);
            }
            #pragma unroll
            for (int j = 0; j < 8; j++) {
                if (j > jmax) continue;
                MMA_BF16(s[j], qh[ks], kbh[j]);
                MMA_BF16(s[j], qh[ks], kbl[j]);
                MMA_BF16(s[j], ql[ks], kbh[j]);
            }
        }

        if (diag) {
            #pragma unroll
            for (int j = 0; j < 8; j++)
                #pragma unroll
                for (int t = 0; t < 4; t++) {
                    int row = w * 16 + g + ((t >> 1) << 3);
                    int col = j * 8 + cq + (t & 1);
                    if (col > row) s[j][t] = -1e30f;
                }
        }

        #pragma unroll
        for (int hr = 0; hr < 2; hr++) {
            float mx = -1e30f;
            #pragma unroll
            for (int j = 0; j < 8; j++)
                mx = fmaxf(mx, fmaxf(s[j][2 * hr], s[j][2 * hr + 1]));
            mx = fmaxf(mx, __shfl_xor_sync(0xffffffffu, mx, 1));
            mx = fmaxf(mx, __shfl_xor_sync(0xffffffffu, mx, 2));
            float mn = fmaxf(m[hr], mx);
            float corr = __expf(m[hr] - mn);
            m[hr] = mn;
            float ls = 0.f;
            #pragma unroll
            for (int j = 0; j < 8; j++) {
                float p0 = __expf(s[j][2 * hr] - mn);
                float p1 = __expf(s[j][2 * hr + 1] - mn);
                s[j][2 * hr] = p0; s[j][2 * hr + 1] = p1;
                ls += p0 + p1;
            }
            ls += __shfl_xor_sync(0xffffffffu, ls, 1);
            ls += __shfl_xor_sync(0xffffffffu, ls, 2);
            l[hr] = l[hr] * corr + ls;
            #pragma unroll
            for (int j = 0; j < 8; j++) {
                accO[j][2 * hr] *= corr;
                accO[j][2 * hr + 1] *= corr;
            }
        }

        #pragma unroll
        for (int j2 = 0; j2 < 4; j2++) {
            uint32_t ah[4], al[4];
            ah[0] = pack2(s[2 * j2][0], s[2 * j2][1]);
            ah[1] = pack2(s[2 * j2][2], s[2 * j2][3]);
            ah[2] = pack2(s[2 * j2 + 1][0], s[2 * j2 + 1][1]);
            ah[3] = pack2(s[2 * j2 + 1][2], s[2 * j2 + 1][3]);
            al[0] = pack2(bf_lo(s[2 * j2][0]), bf_lo(s[2 * j2][1]));
            al[1] = pack2(bf_lo(s[2 * j2][2]), bf_lo(s[2 * j2][3]));
            al[2] = pack2(bf_lo(s[2 * j2 + 1][0]), bf_lo(s[2 * j2 + 1][1]));
            al[3] = pack2(bf_lo(s[2 * j2 + 1][2]), bf_lo(s[2 * j2 + 1][3]));
            #pragma unroll
            for (int jd = 0; jd < 4; jd++) {
                uint32_t off = ((j2 * 16 + (lane & 15)) * AST
                                + jd * 16 + (lane >> 4) * 8) * 2;
                uint32_t vbh[2][2], vbl[2][2];
                LDMATRIX_X4_T(vbh[0][0], vbh[0][1], vbh[1][0], vbh[1][1], pVh + off);
                LDMATRIX_X4_T(vbl[0][0], vbl[0][1], vbl[1][0], vbl[1][1], pVl + off);
                MMA_BF16(accO[2 * jd], ah, vbh[0]);
                MMA_BF16(accO[2 * jd], ah, vbl[0]);
                MMA_BF16(accO[2 * jd], al, vbh[0]);
                MMA_BF16(accO[2 * jd + 1], ah, vbh[1]);
                MMA_BF16(accO[2 * jd + 1], ah, vbl[1]);
                MMA_BF16(accO[2 * jd + 1], al, vbh[1]);
            }
        }
    }

    float inv0 = 1.f / l[0], inv1 = 1.f / l[1];
    #pragma unroll
    for (int j = 0; j < 8; j++) {
        int row = qt * 64 + w * 16 + g;
        int col = h * 64 + j * 8 + cq;
        *(float2*)(y + (size_t)row * DMODEL + col) =
            make_float2(accO[j][0] * inv0, accO[j][1] * inv0);
        *(float2*)(y + (size_t)(row + 8) * DMODEL + col) =
            make_float2(accO[j][2] * inv1, accO[j][3] * inv1);
    }
}

// ---------------------------------------------------------------------------
extern "C" void kernel_launch(void* const* d_in, const int* in_sizes, int n_in,
                              void* d_out, int out_size)
{
    const float* x      = (const float*)d_in[0];
    const float* W_attn = (const float*)d_in[1];
    const float* b_attn = (const float*)d_in[2];
    const float* W_proj = (const float*)d_in[3];
    const float* b_proj = (const float*)d_in[4];
    float* out = (float*)d_out;

    float *qkv, *yb;
    bf16 *xh, *xl, *wh, *wl, *ph, *pl, *yh, *yl, *kh, *kl, *vh, *vl;
    cudaGetSymbolAddress((void**)&qkv, g_qkv);
    cudaGetSymbolAddress((void**)&yb,  g_y);
    cudaGetSymbolAddress((void**)&xh, g_xh); cudaGetSymbolAddress((void**)&xl, g_xl);
    cudaGetSymbolAddress((void**)&wh, g_wh); cudaGetSymbolAddress((void**)&wl, g_wl);
    cudaGetSymbolAddress((void**)&ph, g_ph); cudaGetSymbolAddress((void**)&pl, g_pl);
    cudaGetSymbolAddress((void**)&yh, g_yh); cudaGetSymbolAddress((void**)&yl, g_yl);
    cudaGetSymbolAddress((void**)&kh, g_kh); cudaGetSymbolAddress((void**)&kl, g_kl);
    cudaGetSymbolAddress((void**)&vh, g_vh); cudaGetSymbolAddress((void**)&vl, g_vl);

    cudaFuncSetAttribute(tc_gemm_bias_kernel,
                         cudaFuncAttributeMaxDynamicSharedMemorySize, GEMM_SMEM_BYTES);

    prep_split_kernel<<<T_SEQ * DMODEL / 1024, 256>>>(x, xh, xl);
    prep_split_kernel<<<DMODEL * 3 * DMODEL / 1024, 256>>>(W_attn, wh, wl);
    prep_split_kernel<<<DMODEL * DMODEL / 1024, 256>>>(W_proj, ph, pl);

    // 1) qkv = x @ W_attn + b_attn   [2048 x 3072]
    tc_gemm_bias_kernel<<<dim3(3072 / 64, 2048 / 128), 256, GEMM_SMEM_BYTES>>>(
        xh, xl, wh, wl, b_attn, qkv, DMODEL, 3 * DMODEL);

    prep_kv_kernel<<<T_SEQ * DMODEL / 1024, 256>>>(qkv, kh, kl, vh, vl);

    // 2) y = MLR-attention
    mlr_attn_tc_kernel<<<dim3(T_SEQ / 64, NHEAD), 128>>>(qkv, kh, kl, vh, vl, yb);

    // 3) out = y @ W_proj + b_proj
    prep_split_kernel<<<T_SEQ * DMODEL / 1024, 256>>>(yb, yh, yl);
    tc_gemm_bias_kernel<<<dim3(1024 / 64, 2048 / 128), 256, GEMM_SMEM_BYTES>>>(
        yh, yl, ph, pl, b_proj, out, DMODEL, DMODEL);
}